// round 3
// baseline (speedup 1.0000x reference)
#include <cuda_runtime.h>
#include <cuda_bf16.h>
#include <cstdint>

// ============================================================================
// CrystalAttention on B200, sm_100-baseline ISA (no tcgen05 — toolchain emits
// compute_100 PTX). Algebra:
//   VWt[d][n] = sum_k W[d,k] V[n,k]                        (tiny GEMM)
//   S = X @ P^T ; E = exp(scales/(dist+0.1)) ; dist = sqrt(xsq+psq-2S)
//   out = (E @ VWt^T_over_n) / rowsum(E) + b_out
// x[8,2048,512] -> M=16384, D=512, N=1024.
// ============================================================================
#define MTOT 16384
#define DIM  512
#define NNEU 1024

// ---------------- scratch (__device__ globals; no allocs allowed) -----------
__device__ __nv_bfloat16 g_xb[(size_t)MTOT * DIM];     // x bf16
__device__ float         g_xsq[MTOT];                  // ||x||^2
__device__ __nv_bfloat16 g_pb[(size_t)NNEU * DIM];     // positions bf16
__device__ float         g_psq[NNEU];                  // ||p||^2
__device__ __nv_bfloat16 g_vb[(size_t)NNEU * DIM];     // values bf16
__device__ __nv_bfloat16 g_wb[(size_t)DIM * DIM];      // W_out bf16
__device__ __nv_bfloat16 g_vwt[(size_t)DIM * NNEU];    // VWt[d][n]
__device__ __nv_bfloat16 g_E[(size_t)MTOT * NNEU];     // exp(score)
__device__ float         g_rowsum[MTOT];               // sum_n exp(score)

// ============================================================================
// helpers
// ============================================================================
__device__ __forceinline__ uint32_t smem_u32(const void* p) {
    uint32_t a;
    asm("{ .reg .u64 t; cvta.to.shared.u64 t, %1; cvt.u32.u64 %0, t; }"
        : "=r"(a) : "l"(p));
    return a;
}

#define CP_ASYNC16(saddr, gaddr) \
    asm volatile("cp.async.cg.shared.global [%0], [%1], 16;\n" \
                 :: "r"(saddr), "l"(gaddr) : "memory")
#define CP_COMMIT() asm volatile("cp.async.commit_group;\n" ::: "memory")
#define CP_WAIT1()  asm volatile("cp.async.wait_group 1;\n" ::: "memory")
#define CP_WAIT0()  asm volatile("cp.async.wait_group 0;\n" ::: "memory")

__device__ __forceinline__ void ldsm_x4(uint32_t* f, uint32_t addr) {
    asm volatile("ldmatrix.sync.aligned.m8n8.x4.shared.b16 {%0,%1,%2,%3}, [%4];\n"
                 : "=r"(f[0]), "=r"(f[1]), "=r"(f[2]), "=r"(f[3]) : "r"(addr));
}

__device__ __forceinline__ void mma16816(float* d, const uint32_t* a, const uint32_t* b) {
    asm volatile(
        "mma.sync.aligned.m16n8k16.row.col.f32.bf16.bf16.f32 "
        "{%0,%1,%2,%3}, {%4,%5,%6,%7}, {%8,%9}, {%0,%1,%2,%3};\n"
        : "+f"(d[0]), "+f"(d[1]), "+f"(d[2]), "+f"(d[3])
        : "r"(a[0]), "r"(a[1]), "r"(a[2]), "r"(a[3]), "r"(b[0]), "r"(b[1]));
}

// swizzled smem byte offset for tile row r (128B pitch), b16 col c (c%8==0)
__device__ __forceinline__ uint32_t sw_off(int r, int c) {
    return (uint32_t)(r * 128 + ((((c >> 3) ^ (r & 7))) << 4));
}

// ============================================================================
// K0a: fp32 -> bf16 convert + row sum-of-squares (x / positions)
// ============================================================================
__global__ void k_rowsq(const float* __restrict__ src, int which) {
    __nv_bfloat16* dstB = which ? g_pb : g_xb;
    float* dstS = which ? g_psq : g_xsq;
    int row = blockIdx.x;
    int t = threadIdx.x;
    float4 v = reinterpret_cast<const float4*>(src)[(size_t)row * (DIM / 4) + t];
    __nv_bfloat162 p0 = __floats2bfloat162_rn(v.x, v.y);
    __nv_bfloat162 p1 = __floats2bfloat162_rn(v.z, v.w);
    uint2 u;
    u.x = *reinterpret_cast<uint32_t*>(&p0);
    u.y = *reinterpret_cast<uint32_t*>(&p1);
    reinterpret_cast<uint2*>(dstB)[(size_t)row * (DIM / 4) + t] = u;

    float s = v.x * v.x + v.y * v.y + v.z * v.z + v.w * v.w;
    #pragma unroll
    for (int off = 16; off > 0; off >>= 1)
        s += __shfl_xor_sync(0xffffffffu, s, off);
    __shared__ float ws[4];
    if ((t & 31) == 0) ws[t >> 5] = s;
    __syncthreads();
    if (t == 0) dstS[row] = ws[0] + ws[1] + ws[2] + ws[3];
}

// K0b: plain fp32 -> bf16 convert (values / W_out)
__global__ void k_conv(const float* __restrict__ src, int count4, int which) {
    __nv_bfloat16* dst = which ? g_wb : g_vb;
    for (int i = blockIdx.x * blockDim.x + threadIdx.x; i < count4;
         i += gridDim.x * blockDim.x) {
        float4 v = reinterpret_cast<const float4*>(src)[i];
        __nv_bfloat162 p0 = __floats2bfloat162_rn(v.x, v.y);
        __nv_bfloat162 p1 = __floats2bfloat162_rn(v.z, v.w);
        uint2 u;
        u.x = *reinterpret_cast<uint32_t*>(&p0);
        u.y = *reinterpret_cast<uint32_t*>(&p1);
        reinterpret_cast<uint2*>(dst)[i] = u;
    }
}

// ============================================================================
// Generic 128x128-tile bf16 GEMM: C = A @ B^T, A[M,K] B[N,K] row-major.
// 256 threads, warp grid 4(M) x 2(N), warp tile 32x64, mma.sync m16n8k16.
// Double-buffered cp.async pipeline, K chunk = 64.
// MODE 0: store bf16 to dst (stride NNEU)                 [VWt]
// MODE 1: e = exp(scl[c]/(sqrt(max(xsq[r]+psq[c]-2s,0))+0.1)); bf16 dst   [E]
// MODE 2: o = s / rowsum[r] + bout[c]; f32 dst (stride DIM)               [out]
// ============================================================================
template<int KTOT, int MODE>
__global__ void __launch_bounds__(256, 1) k_gemm(
    const __nv_bfloat16* __restrict__ Ag,
    const __nv_bfloat16* __restrict__ Bg,
    void* __restrict__ dst,
    const float* __restrict__ aux0,   // xsq (M1) / rowsum (M2)
    const float* __restrict__ aux1,   // psq (M1) / bout  (M2)
    const float* __restrict__ aux2)   // scales (M1)
{
    constexpr int NC = KTOT / 64;     // k-chunks
    extern __shared__ char smem[];
    const uint32_t sbase = smem_u32(smem);

    const int tid = threadIdx.x;
    const int lane = tid & 31, wid = tid >> 5;
    const int warpM = wid >> 1, warpN = wid & 1;
    const int m0 = blockIdx.x * 128;
    const int n0 = blockIdx.y * 128;

    // ---- loader: chunk kc -> buffer kc&1 (A 16KB + B 16KB per buffer) ----
    auto prefetch = [&](int kc) {
        const __nv_bfloat16* Ab = Ag + (size_t)m0 * KTOT + kc * 64;
        const __nv_bfloat16* Bb = Bg + (size_t)n0 * KTOT + kc * 64;
        uint32_t da = sbase + (kc & 1) * 32768;
        uint32_t db = da + 16384;
        #pragma unroll
        for (int it = 0; it < 4; it++) {
            int i = tid + it * 256;
            int r = i >> 3, ch = i & 7;
            uint32_t so = sw_off(r, ch * 8);
            CP_ASYNC16(da + so, Ab + (size_t)r * KTOT + ch * 8);
            CP_ASYNC16(db + so, Bb + (size_t)r * KTOT + ch * 8);
        }
        CP_COMMIT();
    };

    float acc[2][8][4];
    #pragma unroll
    for (int i = 0; i < 2; i++)
        #pragma unroll
        for (int j = 0; j < 8; j++)
            #pragma unroll
            for (int k = 0; k < 4; k++) acc[i][j][k] = 0.f;

    prefetch(0);

    for (int c = 0; c < NC; c++) {
        if (c + 1 < NC) { prefetch(c + 1); CP_WAIT1(); }
        else            { CP_WAIT0(); }
        __syncthreads();

        uint32_t sa = sbase + (c & 1) * 32768;
        uint32_t sb = sa + 16384;

        #pragma unroll
        for (int ks = 0; ks < 4; ks++) {
            uint32_t af[2][4], bfr[8][2];
            #pragma unroll
            for (int mi = 0; mi < 2; mi++) {
                int r = warpM * 32 + mi * 16 + (lane & 15);
                int cc = ks * 16 + ((lane >> 4) << 3);
                ldsm_x4(af[mi], sa + sw_off(r, cc));
            }
            #pragma unroll
            for (int nb = 0; nb < 4; nb++) {
                int r = warpN * 64 + nb * 16 + ((lane >> 4) << 3) + (lane & 7);
                int cc = ks * 16 + (((lane >> 3) & 1) << 3);
                uint32_t f[4];
                ldsm_x4(f, sb + sw_off(r, cc));
                bfr[2 * nb][0] = f[0]; bfr[2 * nb][1] = f[1];
                bfr[2 * nb + 1][0] = f[2]; bfr[2 * nb + 1][1] = f[3];
            }
            #pragma unroll
            for (int mi = 0; mi < 2; mi++)
                #pragma unroll
                for (int nj = 0; nj < 8; nj++)
                    mma16816(acc[mi][nj], af[mi], bfr[nj]);
        }
        __syncthreads();
    }

    // ---- epilogue ----
    const int rb = lane >> 2;              // 0..7
    const int cb = (lane & 3) * 2;         // 0,2,4,6

    #pragma unroll
    for (int mi = 0; mi < 2; mi++) {
        int r0 = m0 + warpM * 32 + mi * 16 + rb;   // and r0+8
        #pragma unroll
        for (int nj = 0; nj < 8; nj++) {
            int c0 = n0 + warpN * 64 + nj * 8 + cb;  // and c0+1
            float* a = acc[mi][nj];
            if (MODE == 0) {
                __nv_bfloat16* D = (__nv_bfloat16*)dst;
                *reinterpret_cast<__nv_bfloat162*>(D + (size_t)r0 * NNEU + c0) =
                    __floats2bfloat162_rn(a[0], a[1]);
                *reinterpret_cast<__nv_bfloat162*>(D + (size_t)(r0 + 8) * NNEU + c0) =
                    __floats2bfloat162_rn(a[2], a[3]);
            } else if (MODE == 1) {
                __nv_bfloat16* D = (__nv_bfloat16*)dst;
                float xs0 = aux0[r0], xs1 = aux0[r0 + 8];
                float pq0 = aux1[c0], pq1 = aux1[c0 + 1];
                float sc0 = aux2[c0], sc1 = aux2[c0 + 1];
                float d00 = sqrtf(fmaxf(xs0 + pq0 - 2.f * a[0], 0.f));
                float d01 = sqrtf(fmaxf(xs0 + pq1 - 2.f * a[1], 0.f));
                float d10 = sqrtf(fmaxf(xs1 + pq0 - 2.f * a[2], 0.f));
                float d11 = sqrtf(fmaxf(xs1 + pq1 - 2.f * a[3], 0.f));
                float e00 = __expf(sc0 / (d00 + 0.1f));
                float e01 = __expf(sc1 / (d01 + 0.1f));
                float e10 = __expf(sc0 / (d10 + 0.1f));
                float e11 = __expf(sc1 / (d11 + 0.1f));
                *reinterpret_cast<__nv_bfloat162*>(D + (size_t)r0 * NNEU + c0) =
                    __floats2bfloat162_rn(e00, e01);
                *reinterpret_cast<__nv_bfloat162*>(D + (size_t)(r0 + 8) * NNEU + c0) =
                    __floats2bfloat162_rn(e10, e11);
            } else {
                float* D = (float*)dst;
                float iv0 = 1.f / aux0[r0], iv1 = 1.f / aux0[r0 + 8];
                float b0 = aux1[c0], b1 = aux1[c0 + 1];
                float2 o0 = make_float2(a[0] * iv0 + b0, a[1] * iv0 + b1);
                float2 o1 = make_float2(a[2] * iv1 + b0, a[3] * iv1 + b1);
                *reinterpret_cast<float2*>(D + (size_t)r0 * DIM + c0) = o0;
                *reinterpret_cast<float2*>(D + (size_t)(r0 + 8) * DIM + c0) = o1;
            }
        }
    }
}

// ============================================================================
// rowsum over E (deterministic, one warp per row)
// ============================================================================
__global__ void k_rowsum() {
    int row = blockIdx.x * 8 + (threadIdx.x >> 5);
    int lane = threadIdx.x & 31;
    const uint4* p = reinterpret_cast<const uint4*>(g_E + (size_t)row * NNEU);
    float s = 0.f;
    #pragma unroll
    for (int i = 0; i < 4; i++) {
        uint4 v = p[lane + i * 32];
        uint32_t w[4] = {v.x, v.y, v.z, v.w};
        #pragma unroll
        for (int j = 0; j < 4; j++) {
            __nv_bfloat162 h = *reinterpret_cast<__nv_bfloat162*>(&w[j]);
            float2 f = __bfloat1622float2(h);
            s += f.x + f.y;
        }
    }
    #pragma unroll
    for (int off = 16; off > 0; off >>= 1)
        s += __shfl_xor_sync(0xffffffffu, s, off);
    if (lane == 0) g_rowsum[row] = s;
}

// ============================================================================
// Host launcher
// ============================================================================
extern "C" void kernel_launch(void* const* d_in, const int* in_sizes, int n_in,
                              void* d_out, int out_size) {
    (void)in_sizes; (void)n_in; (void)out_size;
    const float* x      = (const float*)d_in[0];
    const float* pos    = (const float*)d_in[1];
    const float* scales = (const float*)d_in[2];
    const float* values = (const float*)d_in[3];
    const float* W      = (const float*)d_in[4];
    const float* b      = (const float*)d_in[5];
    float* out = (float*)d_out;

    static __nv_bfloat16* vwt_p = nullptr;
    static __nv_bfloat16* E_p   = nullptr;
    static float *xsq_p, *psq_p, *rs_p;
    static __nv_bfloat16 *xb_p, *pb_p, *vb_p, *wb_p;
    if (!vwt_p) {
        cudaGetSymbolAddress((void**)&vwt_p, g_vwt);
        cudaGetSymbolAddress((void**)&E_p,   g_E);
        cudaGetSymbolAddress((void**)&xsq_p, g_xsq);
        cudaGetSymbolAddress((void**)&psq_p, g_psq);
        cudaGetSymbolAddress((void**)&rs_p,  g_rowsum);
        cudaGetSymbolAddress((void**)&xb_p,  g_xb);
        cudaGetSymbolAddress((void**)&pb_p,  g_pb);
        cudaGetSymbolAddress((void**)&vb_p,  g_vb);
        cudaGetSymbolAddress((void**)&wb_p,  g_wb);
        cudaFuncSetAttribute(k_gemm<512, 0>,
            cudaFuncAttributeMaxDynamicSharedMemorySize, 65536);
        cudaFuncSetAttribute(k_gemm<512, 1>,
            cudaFuncAttributeMaxDynamicSharedMemorySize, 65536);
        cudaFuncSetAttribute(k_gemm<1024, 2>,
            cudaFuncAttributeMaxDynamicSharedMemorySize, 65536);
    }

    k_rowsq<<<MTOT, 128>>>(x, 0);
    k_rowsq<<<NNEU, 128>>>(pos, 1);
    k_conv<<<512, 256>>>(values, (NNEU * DIM) / 4, 0);
    k_conv<<<256, 256>>>(W, (DIM * DIM) / 4, 1);

    // VWt[d][n] = sum_k W[d,k] V[n,k]   (M=512, N=1024, K=512)
    k_gemm<512, 0><<<dim3(4, 8), 256, 65536>>>(
        wb_p, vb_p, vwt_p, nullptr, nullptr, nullptr);

    // E = exp(score(X @ P^T))           (M=16384, N=1024, K=512)
    k_gemm<512, 1><<<dim3(128, 8), 256, 65536>>>(
        xb_p, pb_p, E_p, xsq_p, psq_p, scales);

    k_rowsum<<<MTOT / 8, 256>>>();

    // out = E @ VWt^T / rowsum + b      (M=16384, N=512, K=1024)
    k_gemm<1024, 2><<<dim3(128, 4), 256, 65536>>>(
        E_p, vwt_p, out, rs_p, b, nullptr);
}

// round 4
// speedup vs baseline: 1.0612x; 1.0612x over previous
#include <cuda_runtime.h>
#include <cuda_bf16.h>
#include <cstdint>

// ============================================================================
// CrystalAttention, sm_100-baseline ISA (mma.sync + cp.async; no tcgen05).
//   VWt[d][n] = sum_k W[d,k] V[n,k]
//   S = X @ P^T ; E = exp(scales/(sqrt(max(xsq+psq-2S,0))+0.1))
//   out = (E @ VWt^T) / rowsum(E) + b_out
// M=16384, D=512, N=1024.
// R4: 128x256 CTA tile, 64x64 warp tile, 3-stage cp.async, fused rowsum.
// ============================================================================
#define MTOT 16384
#define DIM  512
#define NNEU 1024

__device__ __nv_bfloat16 g_xb[(size_t)MTOT * DIM];
__device__ float         g_xsq[MTOT];
__device__ __nv_bfloat16 g_pb[(size_t)NNEU * DIM];
__device__ float         g_psq[NNEU];
__device__ __nv_bfloat16 g_vb[(size_t)NNEU * DIM];
__device__ __nv_bfloat16 g_wb[(size_t)DIM * DIM];
__device__ __nv_bfloat16 g_vwt[(size_t)DIM * NNEU];
__device__ __nv_bfloat16 g_E[(size_t)MTOT * NNEU];
__device__ float         g_rsp[(size_t)MTOT * 4];   // partial rowsums per nb
__device__ float         g_rowsum[MTOT];

// ============================================================================
// helpers
// ============================================================================
__device__ __forceinline__ uint32_t smem_u32(const void* p) {
    uint32_t a;
    asm("{ .reg .u64 t; cvta.to.shared.u64 t, %1; cvt.u32.u64 %0, t; }"
        : "=r"(a) : "l"(p));
    return a;
}

#define CP_ASYNC16(saddr, gaddr) \
    asm volatile("cp.async.cg.shared.global [%0], [%1], 16;\n" \
                 :: "r"(saddr), "l"(gaddr) : "memory")
#define CP_COMMIT() asm volatile("cp.async.commit_group;\n" ::: "memory")
#define CP_WAIT(n)  asm volatile("cp.async.wait_group %0;\n" :: "n"(n) : "memory")

__device__ __forceinline__ void ldsm_x4(uint32_t* f, uint32_t addr) {
    asm volatile("ldmatrix.sync.aligned.m8n8.x4.shared.b16 {%0,%1,%2,%3}, [%4];\n"
                 : "=r"(f[0]), "=r"(f[1]), "=r"(f[2]), "=r"(f[3]) : "r"(addr));
}

__device__ __forceinline__ void mma16816(float* d, const uint32_t* a, const uint32_t* b) {
    asm volatile(
        "mma.sync.aligned.m16n8k16.row.col.f32.bf16.bf16.f32 "
        "{%0,%1,%2,%3}, {%4,%5,%6,%7}, {%8,%9}, {%0,%1,%2,%3};\n"
        : "+f"(d[0]), "+f"(d[1]), "+f"(d[2]), "+f"(d[3])
        : "r"(a[0]), "r"(a[1]), "r"(a[2]), "r"(a[3]), "r"(b[0]), "r"(b[1]));
}

// swizzled smem byte offset, 128B pitch rows, b16 col c (c%8==0)
__device__ __forceinline__ uint32_t sw_off(int r, int c) {
    return (uint32_t)(r * 128 + ((((c >> 3) ^ (r & 7))) << 4));
}

// ============================================================================
// prep: fp32->bf16 + row sum-of-squares for x (rows < MTOT) and positions
// ============================================================================
__global__ void k_rowsq(const float* __restrict__ x, const float* __restrict__ pos) {
    int row = blockIdx.x;
    const float* src = (row < MTOT) ? x : pos;
    int r = (row < MTOT) ? row : row - MTOT;
    __nv_bfloat16* dstB = (row < MTOT) ? g_xb : g_pb;
    float* dstS = (row < MTOT) ? g_xsq : g_psq;
    int t = threadIdx.x;
    float4 v = reinterpret_cast<const float4*>(src)[(size_t)r * (DIM / 4) + t];
    __nv_bfloat162 p0 = __floats2bfloat162_rn(v.x, v.y);
    __nv_bfloat162 p1 = __floats2bfloat162_rn(v.z, v.w);
    uint2 u;
    u.x = *reinterpret_cast<uint32_t*>(&p0);
    u.y = *reinterpret_cast<uint32_t*>(&p1);
    reinterpret_cast<uint2*>(dstB)[(size_t)r * (DIM / 4) + t] = u;

    float s = v.x * v.x + v.y * v.y + v.z * v.z + v.w * v.w;
    #pragma unroll
    for (int off = 16; off > 0; off >>= 1)
        s += __shfl_xor_sync(0xffffffffu, s, off);
    __shared__ float ws[4];
    if ((t & 31) == 0) ws[t >> 5] = s;
    __syncthreads();
    if (t == 0) dstS[r] = ws[0] + ws[1] + ws[2] + ws[3];
}

// prep: fp32->bf16 for values then W_out, one grid
__global__ void k_conv(const float* __restrict__ values, const float* __restrict__ W) {
    constexpr int NV4 = (NNEU * DIM) / 4;   // 131072
    int i = blockIdx.x * blockDim.x + threadIdx.x;  // grid covers NV4 + NW4
    const float* src;
    __nv_bfloat16* dst;
    int j;
    if (i < NV4) { src = values; dst = g_vb; j = i; }
    else         { src = W;      dst = g_wb; j = i - NV4; }
    float4 v = reinterpret_cast<const float4*>(src)[j];
    __nv_bfloat162 p0 = __floats2bfloat162_rn(v.x, v.y);
    __nv_bfloat162 p1 = __floats2bfloat162_rn(v.z, v.w);
    uint2 u;
    u.x = *reinterpret_cast<uint32_t*>(&p0);
    u.y = *reinterpret_cast<uint32_t*>(&p1);
    reinterpret_cast<uint2*>(dst)[j] = u;
}

// ============================================================================
// GEMM: C = A @ B^T. CTA tile 128(M) x 256(N), K chunk 64, 3-stage cp.async.
// 256 threads: warpM = wid>>2 (2), warpN = wid&3 (4); warp tile 64x64.
// MODE 0: bf16 store (VWt)    MODE 1: E=exp(score), bf16 + partial rowsum
// MODE 2: out = acc/rowsum + b, fp32
// ============================================================================
constexpr int STG    = 49152;            // bytes per stage (A 16KB + B 32KB)
constexpr int SM_RS  = 3 * STG;          // rowsum scratch (128*4 floats)
constexpr int SMEM_SZ = SM_RS + 2048;

template<int KTOT, int MODE>
__global__ void __launch_bounds__(256, 1) k_gemm(
    const __nv_bfloat16* __restrict__ Ag,
    const __nv_bfloat16* __restrict__ Bg,
    void* __restrict__ dst,
    const float* __restrict__ aux0,   // xsq (M1) / rowsum (M2)
    const float* __restrict__ aux1,   // psq (M1) / bout  (M2)
    const float* __restrict__ aux2)   // scales (M1)
{
    constexpr int NC = KTOT / 64;
    extern __shared__ char smem[];
    const uint32_t sbase = smem_u32(smem);

    const int tid = threadIdx.x;
    const int lane = tid & 31, wid = tid >> 5;
    const int warpM = wid >> 2, warpN = wid & 3;
    const int m0 = blockIdx.x * 128;
    const int n0 = blockIdx.y * 256;

    auto prefetch = [&](int kc) {
        const __nv_bfloat16* Ab = Ag + (size_t)m0 * KTOT + kc * 64;
        const __nv_bfloat16* Bb = Bg + (size_t)n0 * KTOT + kc * 64;
        uint32_t da = sbase + (kc % 3) * STG;
        uint32_t db = da + 16384;
        #pragma unroll
        for (int it = 0; it < 4; it++) {          // A: 128 rows x 8 chunks
            int i = tid + it * 256;
            int r = i >> 3, ch = i & 7;
            CP_ASYNC16(da + sw_off(r, ch * 8), Ab + (size_t)r * KTOT + ch * 8);
        }
        #pragma unroll
        for (int it = 0; it < 8; it++) {          // B: 256 rows x 8 chunks
            int i = tid + it * 256;
            int r = i >> 3, ch = i & 7;
            CP_ASYNC16(db + sw_off(r, ch * 8), Bb + (size_t)r * KTOT + ch * 8);
        }
        CP_COMMIT();
    };

    float acc[4][8][4];
    #pragma unroll
    for (int i = 0; i < 4; i++)
        #pragma unroll
        for (int j = 0; j < 8; j++)
            #pragma unroll
            for (int k = 0; k < 4; k++) acc[i][j][k] = 0.f;

    prefetch(0);
    prefetch(1);

    for (int c = 0; c < NC; c++) {
        if (c + 2 < NC) { prefetch(c + 2); CP_WAIT(2); }
        else if (c + 1 < NC) CP_WAIT(1);
        else CP_WAIT(0);
        __syncthreads();

        uint32_t sa = sbase + (c % 3) * STG;
        uint32_t sb = sa + 16384;

        #pragma unroll
        for (int ks = 0; ks < 4; ks++) {
            uint32_t af[4][4], bfr[8][2];
            #pragma unroll
            for (int mi = 0; mi < 4; mi++) {
                int r = warpM * 64 + mi * 16 + (lane & 15);
                int cc = ks * 16 + ((lane >> 4) << 3);
                ldsm_x4(af[mi], sa + sw_off(r, cc));
            }
            #pragma unroll
            for (int nb = 0; nb < 4; nb++) {
                int r = warpN * 64 + nb * 16 + ((lane >> 4) << 3) + (lane & 7);
                int cc = ks * 16 + (((lane >> 3) & 1) << 3);
                uint32_t f[4];
                ldsm_x4(f, sb + sw_off(r, cc));
                bfr[2 * nb][0] = f[0]; bfr[2 * nb][1] = f[1];
                bfr[2 * nb + 1][0] = f[2]; bfr[2 * nb + 1][1] = f[3];
            }
            #pragma unroll
            for (int mi = 0; mi < 4; mi++)
                #pragma unroll
                for (int nj = 0; nj < 8; nj++)
                    mma16816(acc[mi][nj], af[mi], bfr[nj]);
        }
        __syncthreads();
    }

    // ---- epilogue ----
    const int rb = lane >> 2;
    const int cb = (lane & 3) * 2;
    float* rs_sm = reinterpret_cast<float*>(smem + SM_RS);

    #pragma unroll
    for (int mi = 0; mi < 4; mi++) {
        int rt0 = warpM * 64 + mi * 16 + rb;       // row in tile; +8 for second
        int r0 = m0 + rt0;
        float rs0 = 0.f, rs1 = 0.f;
        #pragma unroll
        for (int nj = 0; nj < 8; nj++) {
            int c0 = n0 + warpN * 64 + nj * 8 + cb;
            float* a = acc[mi][nj];
            if (MODE == 0) {
                __nv_bfloat16* D = (__nv_bfloat16*)dst;
                *reinterpret_cast<__nv_bfloat162*>(D + (size_t)r0 * NNEU + c0) =
                    __floats2bfloat162_rn(a[0], a[1]);
                *reinterpret_cast<__nv_bfloat162*>(D + (size_t)(r0 + 8) * NNEU + c0) =
                    __floats2bfloat162_rn(a[2], a[3]);
            } else if (MODE == 1) {
                __nv_bfloat16* D = (__nv_bfloat16*)dst;
                float xs0 = aux0[r0], xs1 = aux0[r0 + 8];
                float pq0 = aux1[c0], pq1 = aux1[c0 + 1];
                float sc0 = aux2[c0], sc1 = aux2[c0 + 1];
                float d00 = sqrtf(fmaxf(xs0 + pq0 - 2.f * a[0], 0.f));
                float d01 = sqrtf(fmaxf(xs0 + pq1 - 2.f * a[1], 0.f));
                float d10 = sqrtf(fmaxf(xs1 + pq0 - 2.f * a[2], 0.f));
                float d11 = sqrtf(fmaxf(xs1 + pq1 - 2.f * a[3], 0.f));
                float e00 = __expf(sc0 / (d00 + 0.1f));
                float e01 = __expf(sc1 / (d01 + 0.1f));
                float e10 = __expf(sc0 / (d10 + 0.1f));
                float e11 = __expf(sc1 / (d11 + 0.1f));
                rs0 += e00 + e01;
                rs1 += e10 + e11;
                *reinterpret_cast<__nv_bfloat162*>(D + (size_t)r0 * NNEU + c0) =
                    __floats2bfloat162_rn(e00, e01);
                *reinterpret_cast<__nv_bfloat162*>(D + (size_t)(r0 + 8) * NNEU + c0) =
                    __floats2bfloat162_rn(e10, e11);
            } else {
                float* D = (float*)dst;
                float iv0 = 1.f / aux0[r0], iv1 = 1.f / aux0[r0 + 8];
                float b0 = aux1[c0], b1 = aux1[c0 + 1];
                float2 o0 = make_float2(a[0] * iv0 + b0, a[1] * iv0 + b1);
                float2 o1 = make_float2(a[2] * iv1 + b0, a[3] * iv1 + b1);
                *reinterpret_cast<float2*>(D + (size_t)r0 * DIM + c0) = o0;
                *reinterpret_cast<float2*>(D + (size_t)(r0 + 8) * DIM + c0) = o1;
            }
        }
        if (MODE == 1) {
            // reduce over the 4 lanes of the quad (cols), leave on lane&3==0
            rs0 += __shfl_xor_sync(0xffffffffu, rs0, 1);
            rs0 += __shfl_xor_sync(0xffffffffu, rs0, 2);
            rs1 += __shfl_xor_sync(0xffffffffu, rs1, 1);
            rs1 += __shfl_xor_sync(0xffffffffu, rs1, 2);
            if ((lane & 3) == 0) {
                rs_sm[rt0 * 4 + warpN] = rs0;
                rs_sm[(rt0 + 8) * 4 + warpN] = rs1;
            }
        }
    }
    if (MODE == 1) {
        __syncthreads();
        if (tid < 128) {
            float4 v = reinterpret_cast<const float4*>(rs_sm)[tid];
            g_rsp[(size_t)(m0 + tid) * 4 + blockIdx.y] = v.x + v.y + v.z + v.w;
        }
    }
}

// final rowsum reduce: 4 partials -> 1
__global__ void k_rs_reduce() {
    int row = blockIdx.x * blockDim.x + threadIdx.x;
    float4 v = reinterpret_cast<const float4*>(g_rsp)[row];
    g_rowsum[row] = v.x + v.y + v.z + v.w;
}

// ============================================================================
// Host launcher
// ============================================================================
extern "C" void kernel_launch(void* const* d_in, const int* in_sizes, int n_in,
                              void* d_out, int out_size) {
    (void)in_sizes; (void)n_in; (void)out_size;
    const float* x      = (const float*)d_in[0];
    const float* pos    = (const float*)d_in[1];
    const float* scales = (const float*)d_in[2];
    const float* values = (const float*)d_in[3];
    const float* W      = (const float*)d_in[4];
    const float* b      = (const float*)d_in[5];
    float* out = (float*)d_out;

    static __nv_bfloat16* vwt_p = nullptr;
    static __nv_bfloat16* E_p   = nullptr;
    static float *xsq_p, *psq_p, *rs_p;
    static __nv_bfloat16 *xb_p, *pb_p, *vb_p, *wb_p;
    if (!vwt_p) {
        cudaGetSymbolAddress((void**)&vwt_p, g_vwt);
        cudaGetSymbolAddress((void**)&E_p,   g_E);
        cudaGetSymbolAddress((void**)&xsq_p, g_xsq);
        cudaGetSymbolAddress((void**)&psq_p, g_psq);
        cudaGetSymbolAddress((void**)&rs_p,  g_rowsum);
        cudaGetSymbolAddress((void**)&xb_p,  g_xb);
        cudaGetSymbolAddress((void**)&pb_p,  g_pb);
        cudaGetSymbolAddress((void**)&vb_p,  g_vb);
        cudaGetSymbolAddress((void**)&wb_p,  g_wb);
        cudaFuncSetAttribute(k_gemm<512, 0>,
            cudaFuncAttributeMaxDynamicSharedMemorySize, SMEM_SZ);
        cudaFuncSetAttribute(k_gemm<512, 1>,
            cudaFuncAttributeMaxDynamicSharedMemorySize, SMEM_SZ);
        cudaFuncSetAttribute(k_gemm<1024, 2>,
            cudaFuncAttributeMaxDynamicSharedMemorySize, SMEM_SZ);
    }

    k_rowsq<<<MTOT + NNEU, 128>>>(x, pos);
    k_conv<<<((NNEU * DIM + DIM * DIM) / 4) / 256, 256>>>(values, W);

    // VWt[d][n] = sum_k W[d,k] V[n,k]   (M=512, N=1024, K=512)
    k_gemm<512, 0><<<dim3(4, 4), 256, SMEM_SZ>>>(
        wb_p, vb_p, vwt_p, nullptr, nullptr, nullptr);

    // E = exp(score(X @ P^T)) + partial rowsums  (M=16384, N=1024, K=512)
    k_gemm<512, 1><<<dim3(128, 4), 256, SMEM_SZ>>>(
        xb_p, pb_p, E_p, xsq_p, psq_p, scales);

    k_rs_reduce<<<MTOT / 256, 256>>>();

    // out = E @ VWt^T / rowsum + b      (M=16384, N=512, K=1024)
    k_gemm<1024, 2><<<dim3(128, 2), 256, SMEM_SZ>>>(
        E_p, vwt_p, out, rs_p, b, nullptr);
}

// round 5
// speedup vs baseline: 1.1558x; 1.0891x over previous
#include <cuda_runtime.h>
#include <cuda_bf16.h>
#include <cstdint>

// ============================================================================
// CrystalAttention, sm_100-baseline ISA (mma.sync + cp.async; no tcgen05).
//   VWt[d][n] = sum_k W[d,k] V[n,k]
//   S = X @ P^T ; E = exp(scales/(sqrt(max(xsq+psq-2S,0))+0.1))
//   out = (E @ VWt^T) / rowsum(E) + b_out
// M=16384, D=512, N=1024.
// R5: 128x256 CTA tile, 512 threads (4x4 warps, 32x64 warp tile),
// 3-stage cp.async, fused rowsum. Target: fix occupancy/issue starvation.
// ============================================================================
#define MTOT 16384
#define DIM  512
#define NNEU 1024

__device__ __nv_bfloat16 g_xb[(size_t)MTOT * DIM];
__device__ float         g_xsq[MTOT];
__device__ __nv_bfloat16 g_pb[(size_t)NNEU * DIM];
__device__ float         g_psq[NNEU];
__device__ __nv_bfloat16 g_vb[(size_t)NNEU * DIM];
__device__ __nv_bfloat16 g_wb[(size_t)DIM * DIM];
__device__ __nv_bfloat16 g_vwt[(size_t)DIM * NNEU];
__device__ __nv_bfloat16 g_E[(size_t)MTOT * NNEU];
__device__ float         g_rsp[(size_t)MTOT * 4];   // partial rowsums per nb
__device__ float         g_rowsum[MTOT];

// ============================================================================
// helpers
// ============================================================================
__device__ __forceinline__ uint32_t smem_u32(const void* p) {
    uint32_t a;
    asm("{ .reg .u64 t; cvta.to.shared.u64 t, %1; cvt.u32.u64 %0, t; }"
        : "=r"(a) : "l"(p));
    return a;
}

#define CP_ASYNC16(saddr, gaddr) \
    asm volatile("cp.async.cg.shared.global [%0], [%1], 16;\n" \
                 :: "r"(saddr), "l"(gaddr) : "memory")
#define CP_COMMIT() asm volatile("cp.async.commit_group;\n" ::: "memory")
#define CP_WAIT(n)  asm volatile("cp.async.wait_group %0;\n" :: "n"(n) : "memory")

__device__ __forceinline__ void ldsm_x4(uint32_t* f, uint32_t addr) {
    asm volatile("ldmatrix.sync.aligned.m8n8.x4.shared.b16 {%0,%1,%2,%3}, [%4];\n"
                 : "=r"(f[0]), "=r"(f[1]), "=r"(f[2]), "=r"(f[3]) : "r"(addr));
}

__device__ __forceinline__ void mma16816(float* d, const uint32_t* a, const uint32_t* b) {
    asm volatile(
        "mma.sync.aligned.m16n8k16.row.col.f32.bf16.bf16.f32 "
        "{%0,%1,%2,%3}, {%4,%5,%6,%7}, {%8,%9}, {%0,%1,%2,%3};\n"
        : "+f"(d[0]), "+f"(d[1]), "+f"(d[2]), "+f"(d[3])
        : "r"(a[0]), "r"(a[1]), "r"(a[2]), "r"(a[3]), "r"(b[0]), "r"(b[1]));
}

// swizzled smem byte offset, 128B pitch rows, b16 col c (c%8==0)
__device__ __forceinline__ uint32_t sw_off(int r, int c) {
    return (uint32_t)(r * 128 + ((((c >> 3) ^ (r & 7))) << 4));
}

// ============================================================================
// prep: fp32->bf16 + row sum-of-squares for x (rows < MTOT) and positions
// ============================================================================
__global__ void k_rowsq(const float* __restrict__ x, const float* __restrict__ pos) {
    int row = blockIdx.x;
    const float* src = (row < MTOT) ? x : pos;
    int r = (row < MTOT) ? row : row - MTOT;
    __nv_bfloat16* dstB = (row < MTOT) ? g_xb : g_pb;
    float* dstS = (row < MTOT) ? g_xsq : g_psq;
    int t = threadIdx.x;
    float4 v = reinterpret_cast<const float4*>(src)[(size_t)r * (DIM / 4) + t];
    __nv_bfloat162 p0 = __floats2bfloat162_rn(v.x, v.y);
    __nv_bfloat162 p1 = __floats2bfloat162_rn(v.z, v.w);
    uint2 u;
    u.x = *reinterpret_cast<uint32_t*>(&p0);
    u.y = *reinterpret_cast<uint32_t*>(&p1);
    reinterpret_cast<uint2*>(dstB)[(size_t)r * (DIM / 4) + t] = u;

    float s = v.x * v.x + v.y * v.y + v.z * v.z + v.w * v.w;
    #pragma unroll
    for (int off = 16; off > 0; off >>= 1)
        s += __shfl_xor_sync(0xffffffffu, s, off);
    __shared__ float ws[4];
    if ((t & 31) == 0) ws[t >> 5] = s;
    __syncthreads();
    if (t == 0) dstS[r] = ws[0] + ws[1] + ws[2] + ws[3];
}

// prep: fp32->bf16 for values then W_out, one grid
__global__ void k_conv(const float* __restrict__ values, const float* __restrict__ W) {
    constexpr int NV4 = (NNEU * DIM) / 4;   // 131072
    int i = blockIdx.x * blockDim.x + threadIdx.x;
    const float* src;
    __nv_bfloat16* dst;
    int j;
    if (i < NV4) { src = values; dst = g_vb; j = i; }
    else         { src = W;      dst = g_wb; j = i - NV4; }
    float4 v = reinterpret_cast<const float4*>(src)[j];
    __nv_bfloat162 p0 = __floats2bfloat162_rn(v.x, v.y);
    __nv_bfloat162 p1 = __floats2bfloat162_rn(v.z, v.w);
    uint2 u;
    u.x = *reinterpret_cast<uint32_t*>(&p0);
    u.y = *reinterpret_cast<uint32_t*>(&p1);
    reinterpret_cast<uint2*>(dst)[j] = u;
}

// ============================================================================
// GEMM: C = A @ B^T. CTA tile 128(M) x 256(N), K chunk 64, 3-stage cp.async.
// 512 threads: warpM = wid>>2 (4), warpN = wid&3 (4); warp tile 32x64.
// MODE 0: bf16 store (VWt)    MODE 1: E=exp(score), bf16 + partial rowsum
// MODE 2: out = acc/rowsum + b, fp32
// ============================================================================
constexpr int STG    = 49152;            // bytes per stage (A 16KB + B 32KB)
constexpr int SM_RS  = 3 * STG;          // rowsum scratch (128*4 floats)
constexpr int SMEM_SZ = SM_RS + 2048;

template<int KTOT, int MODE>
__global__ void __launch_bounds__(512, 1) k_gemm(
    const __nv_bfloat16* __restrict__ Ag,
    const __nv_bfloat16* __restrict__ Bg,
    void* __restrict__ dst,
    const float* __restrict__ aux0,   // xsq (M1) / rowsum (M2)
    const float* __restrict__ aux1,   // psq (M1) / bout  (M2)
    const float* __restrict__ aux2)   // scales (M1)
{
    constexpr int NC = KTOT / 64;
    extern __shared__ char smem[];
    const uint32_t sbase = smem_u32(smem);

    const int tid = threadIdx.x;
    const int lane = tid & 31, wid = tid >> 5;
    const int warpM = wid >> 2, warpN = wid & 3;
    const int m0 = blockIdx.x * 128;
    const int n0 = blockIdx.y * 256;

    auto prefetch = [&](int kc) {
        const __nv_bfloat16* Ab = Ag + (size_t)m0 * KTOT + kc * 64;
        const __nv_bfloat16* Bb = Bg + (size_t)n0 * KTOT + kc * 64;
        uint32_t da = sbase + (kc % 3) * STG;
        uint32_t db = da + 16384;
        #pragma unroll
        for (int it = 0; it < 2; it++) {          // A: 128 rows x 8 chunks
            int i = tid + it * 512;
            int r = i >> 3, ch = i & 7;
            CP_ASYNC16(da + sw_off(r, ch * 8), Ab + (size_t)r * KTOT + ch * 8);
        }
        #pragma unroll
        for (int it = 0; it < 4; it++) {          // B: 256 rows x 8 chunks
            int i = tid + it * 512;
            int r = i >> 3, ch = i & 7;
            CP_ASYNC16(db + sw_off(r, ch * 8), Bb + (size_t)r * KTOT + ch * 8);
        }
        CP_COMMIT();
    };

    float acc[2][8][4];
    #pragma unroll
    for (int i = 0; i < 2; i++)
        #pragma unroll
        for (int j = 0; j < 8; j++)
            #pragma unroll
            for (int k = 0; k < 4; k++) acc[i][j][k] = 0.f;

    prefetch(0);
    prefetch(1);

    for (int c = 0; c < NC; c++) {
        if (c + 2 < NC) { prefetch(c + 2); CP_WAIT(2); }
        else if (c + 1 < NC) CP_WAIT(1);
        else CP_WAIT(0);
        __syncthreads();

        uint32_t sa = sbase + (c % 3) * STG;
        uint32_t sb = sa + 16384;

        #pragma unroll
        for (int ks = 0; ks < 4; ks++) {
            uint32_t af[2][4], bfr[8][2];
            #pragma unroll
            for (int mi = 0; mi < 2; mi++) {
                int r = warpM * 32 + mi * 16 + (lane & 15);
                int cc = ks * 16 + ((lane >> 4) << 3);
                ldsm_x4(af[mi], sa + sw_off(r, cc));
            }
            #pragma unroll
            for (int nb = 0; nb < 4; nb++) {
                int r = warpN * 64 + nb * 16 + ((lane >> 4) << 3) + (lane & 7);
                int cc = ks * 16 + (((lane >> 3) & 1) << 3);
                uint32_t f[4];
                ldsm_x4(f, sb + sw_off(r, cc));
                bfr[2 * nb][0] = f[0]; bfr[2 * nb][1] = f[1];
                bfr[2 * nb + 1][0] = f[2]; bfr[2 * nb + 1][1] = f[3];
            }
            #pragma unroll
            for (int mi = 0; mi < 2; mi++)
                #pragma unroll
                for (int nj = 0; nj < 8; nj++)
                    mma16816(acc[mi][nj], af[mi], bfr[nj]);
        }
        __syncthreads();
    }

    // ---- epilogue ----
    const int rb = lane >> 2;
    const int cb = (lane & 3) * 2;
    float* rs_sm = reinterpret_cast<float*>(smem + SM_RS);

    #pragma unroll
    for (int mi = 0; mi < 2; mi++) {
        int rt0 = warpM * 32 + mi * 16 + rb;       // row in tile; +8 for second
        int r0 = m0 + rt0;
        float rs0 = 0.f, rs1 = 0.f;
        #pragma unroll
        for (int nj = 0; nj < 8; nj++) {
            int c0 = n0 + warpN * 64 + nj * 8 + cb;
            float* a = acc[mi][nj];
            if (MODE == 0) {
                __nv_bfloat16* D = (__nv_bfloat16*)dst;
                *reinterpret_cast<__nv_bfloat162*>(D + (size_t)r0 * NNEU + c0) =
                    __floats2bfloat162_rn(a[0], a[1]);
                *reinterpret_cast<__nv_bfloat162*>(D + (size_t)(r0 + 8) * NNEU + c0) =
                    __floats2bfloat162_rn(a[2], a[3]);
            } else if (MODE == 1) {
                __nv_bfloat16* D = (__nv_bfloat16*)dst;
                float xs0 = aux0[r0], xs1 = aux0[r0 + 8];
                float pq0 = aux1[c0], pq1 = aux1[c0 + 1];
                float sc0 = aux2[c0], sc1 = aux2[c0 + 1];
                float d00 = sqrtf(fmaxf(xs0 + pq0 - 2.f * a[0], 0.f));
                float d01 = sqrtf(fmaxf(xs0 + pq1 - 2.f * a[1], 0.f));
                float d10 = sqrtf(fmaxf(xs1 + pq0 - 2.f * a[2], 0.f));
                float d11 = sqrtf(fmaxf(xs1 + pq1 - 2.f * a[3], 0.f));
                float e00 = __expf(sc0 / (d00 + 0.1f));
                float e01 = __expf(sc1 / (d01 + 0.1f));
                float e10 = __expf(sc0 / (d10 + 0.1f));
                float e11 = __expf(sc1 / (d11 + 0.1f));
                rs0 += e00 + e01;
                rs1 += e10 + e11;
                *reinterpret_cast<__nv_bfloat162*>(D + (size_t)r0 * NNEU + c0) =
                    __floats2bfloat162_rn(e00, e01);
                *reinterpret_cast<__nv_bfloat162*>(D + (size_t)(r0 + 8) * NNEU + c0) =
                    __floats2bfloat162_rn(e10, e11);
            } else {
                float* D = (float*)dst;
                float iv0 = 1.f / aux0[r0], iv1 = 1.f / aux0[r0 + 8];
                float b0 = aux1[c0], b1 = aux1[c0 + 1];
                float2 o0 = make_float2(a[0] * iv0 + b0, a[1] * iv0 + b1);
                float2 o1 = make_float2(a[2] * iv1 + b0, a[3] * iv1 + b1);
                *reinterpret_cast<float2*>(D + (size_t)r0 * DIM + c0) = o0;
                *reinterpret_cast<float2*>(D + (size_t)(r0 + 8) * DIM + c0) = o1;
            }
        }
        if (MODE == 1) {
            // reduce over the 4 lanes of the quad (cols), leave on lane&3==0
            rs0 += __shfl_xor_sync(0xffffffffu, rs0, 1);
            rs0 += __shfl_xor_sync(0xffffffffu, rs0, 2);
            rs1 += __shfl_xor_sync(0xffffffffu, rs1, 1);
            rs1 += __shfl_xor_sync(0xffffffffu, rs1, 2);
            if ((lane & 3) == 0) {
                rs_sm[rt0 * 4 + warpN] = rs0;
                rs_sm[(rt0 + 8) * 4 + warpN] = rs1;
            }
        }
    }
    if (MODE == 1) {
        __syncthreads();
        if (tid < 128) {
            float4 v = reinterpret_cast<const float4*>(rs_sm)[tid];
            g_rsp[(size_t)(m0 + tid) * 4 + blockIdx.y] = v.x + v.y + v.z + v.w;
        }
    }
}

// final rowsum reduce: 4 partials -> 1
__global__ void k_rs_reduce() {
    int row = blockIdx.x * blockDim.x + threadIdx.x;
    float4 v = reinterpret_cast<const float4*>(g_rsp)[row];
    g_rowsum[row] = v.x + v.y + v.z + v.w;
}

// ============================================================================
// Host launcher
// ============================================================================
extern "C" void kernel_launch(void* const* d_in, const int* in_sizes, int n_in,
                              void* d_out, int out_size) {
    (void)in_sizes; (void)n_in; (void)out_size;
    const float* x      = (const float*)d_in[0];
    const float* pos    = (const float*)d_in[1];
    const float* scales = (const float*)d_in[2];
    const float* values = (const float*)d_in[3];
    const float* W      = (const float*)d_in[4];
    const float* b      = (const float*)d_in[5];
    float* out = (float*)d_out;

    static __nv_bfloat16* vwt_p = nullptr;
    static __nv_bfloat16* E_p   = nullptr;
    static float *xsq_p, *psq_p, *rs_p;
    static __nv_bfloat16 *xb_p, *pb_p, *vb_p, *wb_p;
    if (!vwt_p) {
        cudaGetSymbolAddress((void**)&vwt_p, g_vwt);
        cudaGetSymbolAddress((void**)&E_p,   g_E);
        cudaGetSymbolAddress((void**)&xsq_p, g_xsq);
        cudaGetSymbolAddress((void**)&psq_p, g_psq);
        cudaGetSymbolAddress((void**)&rs_p,  g_rowsum);
        cudaGetSymbolAddress((void**)&xb_p,  g_xb);
        cudaGetSymbolAddress((void**)&pb_p,  g_pb);
        cudaGetSymbolAddress((void**)&vb_p,  g_vb);
        cudaGetSymbolAddress((void**)&wb_p,  g_wb);
        cudaFuncSetAttribute(k_gemm<512, 0>,
            cudaFuncAttributeMaxDynamicSharedMemorySize, SMEM_SZ);
        cudaFuncSetAttribute(k_gemm<512, 1>,
            cudaFuncAttributeMaxDynamicSharedMemorySize, SMEM_SZ);
        cudaFuncSetAttribute(k_gemm<1024, 2>,
            cudaFuncAttributeMaxDynamicSharedMemorySize, SMEM_SZ);
    }

    k_rowsq<<<MTOT + NNEU, 128>>>(x, pos);
    k_conv<<<((NNEU * DIM + DIM * DIM) / 4) / 256, 256>>>(values, W);

    // VWt[d][n] = sum_k W[d,k] V[n,k]   (M=512, N=1024, K=512)
    k_gemm<512, 0><<<dim3(4, 4), 512, SMEM_SZ>>>(
        wb_p, vb_p, vwt_p, nullptr, nullptr, nullptr);

    // E = exp(score(X @ P^T)) + partial rowsums  (M=16384, N=1024, K=512)
    k_gemm<512, 1><<<dim3(128, 4), 512, SMEM_SZ>>>(
        xb_p, pb_p, E_p, xsq_p, psq_p, scales);

    k_rs_reduce<<<MTOT / 256, 256>>>();

    // out = E @ VWt^T / rowsum + b      (M=16384, N=512, K=1024)
    k_gemm<1024, 2><<<dim3(128, 2), 512, SMEM_SZ>>>(
        E_p, vwt_p, out, rs_p, b, nullptr);
}

// round 7
// speedup vs baseline: 1.3687x; 1.1842x over previous
#include <cuda_runtime.h>
#include <cuda_bf16.h>
#include <cstdint>

// ============================================================================
// CrystalAttention, sm_100-baseline ISA (mma.sync + cp.async; no tcgen05).
//   VWt[d][n] = sum_k W[d,k] V[n,k]
//   S = X @ P^T ; E = exp(scales/(sqrt(max(xsq+psq-2S,0))+0.1))
//   out = (E @ VWt^T) / rowsum(E) + b_out
// M=16384, D=512, N=1024.
// R6: 128x128 CTA tile, 256 threads (4x2 warps, 32x64 warp tile), 3-stage
// cp.async with SINGLE sync per chunk, 2 CTAs/SM (__launch_bounds__(256,2)).
// ============================================================================
#define MTOT 16384
#define DIM  512
#define NNEU 1024

__device__ __nv_bfloat16 g_xb[(size_t)MTOT * DIM];
__device__ float         g_xsq[MTOT];
__device__ __nv_bfloat16 g_pb[(size_t)NNEU * DIM];
__device__ float         g_psq[NNEU];
__device__ __nv_bfloat16 g_vb[(size_t)NNEU * DIM];
__device__ __nv_bfloat16 g_wb[(size_t)DIM * DIM];
__device__ __nv_bfloat16 g_vwt[(size_t)DIM * NNEU];
__device__ __nv_bfloat16 g_E[(size_t)MTOT * NNEU];
__device__ float         g_rsp[(size_t)MTOT * 8];   // partial rowsums per nb
__device__ float         g_rowsum[MTOT];

// ============================================================================
// helpers
// ============================================================================
__device__ __forceinline__ uint32_t smem_u32(const void* p) {
    uint32_t a;
    asm("{ .reg .u64 t; cvta.to.shared.u64 t, %1; cvt.u32.u64 %0, t; }"
        : "=r"(a) : "l"(p));
    return a;
}

#define CP_ASYNC16(saddr, gaddr) \
    asm volatile("cp.async.cg.shared.global [%0], [%1], 16;\n" \
                 :: "r"(saddr), "l"(gaddr) : "memory")
#define CP_COMMIT() asm volatile("cp.async.commit_group;\n" ::: "memory")
#define CP_WAIT(n)  asm volatile("cp.async.wait_group %0;\n" :: "n"(n) : "memory")

__device__ __forceinline__ void ldsm_x4(uint32_t* f, uint32_t addr) {
    asm volatile("ldmatrix.sync.aligned.m8n8.x4.shared.b16 {%0,%1,%2,%3}, [%4];\n"
                 : "=r"(f[0]), "=r"(f[1]), "=r"(f[2]), "=r"(f[3]) : "r"(addr));
}

__device__ __forceinline__ void mma16816(float* d, const uint32_t* a, const uint32_t* b) {
    asm volatile(
        "mma.sync.aligned.m16n8k16.row.col.f32.bf16.bf16.f32 "
        "{%0,%1,%2,%3}, {%4,%5,%6,%7}, {%8,%9}, {%0,%1,%2,%3};\n"
        : "+f"(d[0]), "+f"(d[1]), "+f"(d[2]), "+f"(d[3])
        : "r"(a[0]), "r"(a[1]), "r"(a[2]), "r"(a[3]), "r"(b[0]), "r"(b[1]));
}

// swizzled smem byte offset, 128B pitch rows, b16 col c (c%8==0)
__device__ __forceinline__ uint32_t sw_off(int r, int c) {
    return (uint32_t)(r * 128 + ((((c >> 3) ^ (r & 7))) << 4));
}

// ============================================================================
// prep: fp32->bf16 + row sum-of-squares for x (rows < MTOT) and positions
// ============================================================================
__global__ void k_rowsq(const float* __restrict__ x, const float* __restrict__ pos) {
    int row = blockIdx.x;
    const float* src = (row < MTOT) ? x : pos;
    int r = (row < MTOT) ? row : row - MTOT;
    __nv_bfloat16* dstB = (row < MTOT) ? g_xb : g_pb;
    float* dstS = (row < MTOT) ? g_xsq : g_psq;
    int t = threadIdx.x;
    float4 v = reinterpret_cast<const float4*>(src)[(size_t)r * (DIM / 4) + t];
    __nv_bfloat162 p0 = __floats2bfloat162_rn(v.x, v.y);
    __nv_bfloat162 p1 = __floats2bfloat162_rn(v.z, v.w);
    uint2 u;
    u.x = *reinterpret_cast<uint32_t*>(&p0);
    u.y = *reinterpret_cast<uint32_t*>(&p1);
    reinterpret_cast<uint2*>(dstB)[(size_t)r * (DIM / 4) + t] = u;

    float s = v.x * v.x + v.y * v.y + v.z * v.z + v.w * v.w;
    #pragma unroll
    for (int off = 16; off > 0; off >>= 1)
        s += __shfl_xor_sync(0xffffffffu, s, off);
    __shared__ float ws[4];
    if ((t & 31) == 0) ws[t >> 5] = s;
    __syncthreads();
    if (t == 0) dstS[r] = ws[0] + ws[1] + ws[2] + ws[3];
}

// prep: fp32->bf16 for values then W_out, one grid
__global__ void k_conv(const float* __restrict__ values, const float* __restrict__ W) {
    constexpr int NV4 = (NNEU * DIM) / 4;   // 131072
    int i = blockIdx.x * blockDim.x + threadIdx.x;
    const float* src;
    __nv_bfloat16* dst;
    int j;
    if (i < NV4) { src = values; dst = g_vb; j = i; }
    else         { src = W;      dst = g_wb; j = i - NV4; }
    float4 v = reinterpret_cast<const float4*>(src)[j];
    __nv_bfloat162 p0 = __floats2bfloat162_rn(v.x, v.y);
    __nv_bfloat162 p1 = __floats2bfloat162_rn(v.z, v.w);
    uint2 u;
    u.x = *reinterpret_cast<uint32_t*>(&p0);
    u.y = *reinterpret_cast<uint32_t*>(&p1);
    reinterpret_cast<uint2*>(dst)[j] = u;
}

// ============================================================================
// GEMM: C = A @ B^T. CTA tile 128(M) x 128(N), K chunk 64, 3-stage cp.async,
// single __syncthreads per chunk. 256 threads: warpM = wid>>1 (4),
// warpN = wid&1 (2); warp tile 32x64.
// MODE 0: bf16 store (VWt)    MODE 1: E=exp(score), bf16 + partial rowsum
// MODE 2: out = acc/rowsum + b, fp32
// ============================================================================
constexpr int STG    = 32768;            // bytes per stage (A 16KB + B 16KB)
constexpr int SM_RS  = 3 * STG;          // rowsum scratch (128*2 floats)
constexpr int SMEM_SZ = SM_RS + 1024;

template<int KTOT, int MODE>
__global__ void __launch_bounds__(256, 2) k_gemm(
    const __nv_bfloat16* __restrict__ Ag,
    const __nv_bfloat16* __restrict__ Bg,
    void* __restrict__ dst,
    const float* __restrict__ aux0,   // xsq (M1) / rowsum (M2)
    const float* __restrict__ aux1,   // psq (M1) / bout  (M2)
    const float* __restrict__ aux2)   // scales (M1)
{
    constexpr int NC = KTOT / 64;
    extern __shared__ char smem[];
    const uint32_t sbase = smem_u32(smem);

    const int tid = threadIdx.x;
    const int lane = tid & 31, wid = tid >> 5;
    const int warpM = wid >> 1, warpN = wid & 1;
    const int m0 = blockIdx.x * 128;
    const int n0 = blockIdx.y * 128;

    auto prefetch = [&](int kc) {
        const __nv_bfloat16* Ab = Ag + (size_t)m0 * KTOT + kc * 64;
        const __nv_bfloat16* Bb = Bg + (size_t)n0 * KTOT + kc * 64;
        uint32_t da = sbase + (kc % 3) * STG;
        uint32_t db = da + 16384;
        #pragma unroll
        for (int it = 0; it < 4; it++) {          // A: 128 rows x 8 chunks
            int i = tid + it * 256;
            int r = i >> 3, ch = i & 7;
            CP_ASYNC16(da + sw_off(r, ch * 8), Ab + (size_t)r * KTOT + ch * 8);
        }
        #pragma unroll
        for (int it = 0; it < 4; it++) {          // B: 128 rows x 8 chunks
            int i = tid + it * 256;
            int r = i >> 3, ch = i & 7;
            CP_ASYNC16(db + sw_off(r, ch * 8), Bb + (size_t)r * KTOT + ch * 8);
        }
        CP_COMMIT();
    };

    float acc[2][8][4];
    #pragma unroll
    for (int i = 0; i < 2; i++)
        #pragma unroll
        for (int j = 0; j < 8; j++)
            #pragma unroll
            for (int k = 0; k < 4; k++) acc[i][j][k] = 0.f;

    prefetch(0);
    prefetch(1);

    for (int c = 0; c < NC; c++) {
        if (c + 1 < NC) CP_WAIT(1);
        else            CP_WAIT(0);
        __syncthreads();
        // Safe: the sync above proves every warp finished chunk c-1, whose
        // buffer (c-1)%3 == (c+2)%3 is exactly the prefetch target.
        if (c + 2 < NC) prefetch(c + 2);

        uint32_t sa = sbase + (c % 3) * STG;
        uint32_t sb = sa + 16384;

        #pragma unroll
        for (int ks = 0; ks < 4; ks++) {
            uint32_t af[2][4], bfr[8][2];
            #pragma unroll
            for (int mi = 0; mi < 2; mi++) {
                int r = warpM * 32 + mi * 16 + (lane & 15);
                int cc = ks * 16 + ((lane >> 4) << 3);
                ldsm_x4(af[mi], sa + sw_off(r, cc));
            }
            #pragma unroll
            for (int nb = 0; nb < 4; nb++) {
                int r = warpN * 64 + nb * 16 + ((lane >> 4) << 3) + (lane & 7);
                int cc = ks * 16 + (((lane >> 3) & 1) << 3);
                uint32_t f[4];
                ldsm_x4(f, sb + sw_off(r, cc));
                bfr[2 * nb][0] = f[0]; bfr[2 * nb][1] = f[1];
                bfr[2 * nb + 1][0] = f[2]; bfr[2 * nb + 1][1] = f[3];
            }
            #pragma unroll
            for (int mi = 0; mi < 2; mi++)
                #pragma unroll
                for (int nj = 0; nj < 8; nj++)
                    mma16816(acc[mi][nj], af[mi], bfr[nj]);
        }
    }
    __syncthreads();

    // ---- epilogue ----
    const int rb = lane >> 2;
    const int cb = (lane & 3) * 2;
    float* rs_sm = reinterpret_cast<float*>(smem + SM_RS);

    #pragma unroll
    for (int mi = 0; mi < 2; mi++) {
        int rt0 = warpM * 32 + mi * 16 + rb;       // row in tile; +8 for second
        int r0 = m0 + rt0;
        float rs0 = 0.f, rs1 = 0.f;
        #pragma unroll
        for (int nj = 0; nj < 8; nj++) {
            int c0 = n0 + warpN * 64 + nj * 8 + cb;
            float* a = acc[mi][nj];
            if (MODE == 0) {
                __nv_bfloat16* D = (__nv_bfloat16*)dst;
                *reinterpret_cast<__nv_bfloat162*>(D + (size_t)r0 * NNEU + c0) =
                    __floats2bfloat162_rn(a[0], a[1]);
                *reinterpret_cast<__nv_bfloat162*>(D + (size_t)(r0 + 8) * NNEU + c0) =
                    __floats2bfloat162_rn(a[2], a[3]);
            } else if (MODE == 1) {
                __nv_bfloat16* D = (__nv_bfloat16*)dst;
                float xs0 = aux0[r0], xs1 = aux0[r0 + 8];
                float pq0 = aux1[c0], pq1 = aux1[c0 + 1];
                float sc0 = aux2[c0], sc1 = aux2[c0 + 1];
                float d00 = sqrtf(fmaxf(xs0 + pq0 - 2.f * a[0], 0.f));
                float d01 = sqrtf(fmaxf(xs0 + pq1 - 2.f * a[1], 0.f));
                float d10 = sqrtf(fmaxf(xs1 + pq0 - 2.f * a[2], 0.f));
                float d11 = sqrtf(fmaxf(xs1 + pq1 - 2.f * a[3], 0.f));
                float e00 = __expf(sc0 / (d00 + 0.1f));
                float e01 = __expf(sc1 / (d01 + 0.1f));
                float e10 = __expf(sc0 / (d10 + 0.1f));
                float e11 = __expf(sc1 / (d11 + 0.1f));
                rs0 += e00 + e01;
                rs1 += e10 + e11;
                *reinterpret_cast<__nv_bfloat162*>(D + (size_t)r0 * NNEU + c0) =
                    __floats2bfloat162_rn(e00, e01);
                *reinterpret_cast<__nv_bfloat162*>(D + (size_t)(r0 + 8) * NNEU + c0) =
                    __floats2bfloat162_rn(e10, e11);
            } else {
                float* D = (float*)dst;
                float iv0 = 1.f / aux0[r0], iv1 = 1.f / aux0[r0 + 8];
                float b0 = aux1[c0], b1 = aux1[c0 + 1];
                float2 o0 = make_float2(a[0] * iv0 + b0, a[1] * iv0 + b1);
                float2 o1 = make_float2(a[2] * iv1 + b0, a[3] * iv1 + b1);
                *reinterpret_cast<float2*>(D + (size_t)r0 * DIM + c0) = o0;
                *reinterpret_cast<float2*>(D + (size_t)(r0 + 8) * DIM + c0) = o1;
            }
        }
        if (MODE == 1) {
            // reduce over the 4 lanes of the quad (cols), leave on lane&3==0
            rs0 += __shfl_xor_sync(0xffffffffu, rs0, 1);
            rs0 += __shfl_xor_sync(0xffffffffu, rs0, 2);
            rs1 += __shfl_xor_sync(0xffffffffu, rs1, 1);
            rs1 += __shfl_xor_sync(0xffffffffu, rs1, 2);
            if ((lane & 3) == 0) {
                rs_sm[rt0 * 2 + warpN] = rs0;
                rs_sm[(rt0 + 8) * 2 + warpN] = rs1;
            }
        }
    }
    if (MODE == 1) {
        __syncthreads();
        if (tid < 128) {
            float2 v = reinterpret_cast<const float2*>(rs_sm)[tid];
            g_rsp[(size_t)(m0 + tid) * 8 + blockIdx.y] = v.x + v.y;
        }
    }
}

// final rowsum reduce: 8 partials -> 1
__global__ void k_rs_reduce() {
    int row = blockIdx.x * blockDim.x + threadIdx.x;
    float4 v0 = reinterpret_cast<const float4*>(g_rsp)[row * 2];
    float4 v1 = reinterpret_cast<const float4*>(g_rsp)[row * 2 + 1];
    g_rowsum[row] = (v0.x + v0.y + v0.z + v0.w) + (v1.x + v1.y + v1.z + v1.w);
}

// ============================================================================
// Host launcher
// ============================================================================
extern "C" void kernel_launch(void* const* d_in, const int* in_sizes, int n_in,
                              void* d_out, int out_size) {
    (void)in_sizes; (void)n_in; (void)out_size;
    const float* x      = (const float*)d_in[0];
    const float* pos    = (const float*)d_in[1];
    const float* scales = (const float*)d_in[2];
    const float* values = (const float*)d_in[3];
    const float* W      = (const float*)d_in[4];
    const float* b      = (const float*)d_in[5];
    float* out = (float*)d_out;

    static __nv_bfloat16* vwt_p = nullptr;
    static __nv_bfloat16* E_p   = nullptr;
    static float *xsq_p, *psq_p, *rs_p;
    static __nv_bfloat16 *xb_p, *pb_p, *vb_p, *wb_p;
    if (!vwt_p) {
        cudaGetSymbolAddress((void**)&vwt_p, g_vwt);
        cudaGetSymbolAddress((void**)&E_p,   g_E);
        cudaGetSymbolAddress((void**)&xsq_p, g_xsq);
        cudaGetSymbolAddress((void**)&psq_p, g_psq);
        cudaGetSymbolAddress((void**)&rs_p,  g_rowsum);
        cudaGetSymbolAddress((void**)&xb_p,  g_xb);
        cudaGetSymbolAddress((void**)&pb_p,  g_pb);
        cudaGetSymbolAddress((void**)&vb_p,  g_vb);
        cudaGetSymbolAddress((void**)&wb_p,  g_wb);
        cudaFuncSetAttribute(k_gemm<512, 0>,
            cudaFuncAttributeMaxDynamicSharedMemorySize, SMEM_SZ);
        cudaFuncSetAttribute(k_gemm<512, 1>,
            cudaFuncAttributeMaxDynamicSharedMemorySize, SMEM_SZ);
        cudaFuncSetAttribute(k_gemm<1024, 2>,
            cudaFuncAttributeMaxDynamicSharedMemorySize, SMEM_SZ);
    }

    k_rowsq<<<MTOT + NNEU, 128>>>(x, pos);
    k_conv<<<((NNEU * DIM + DIM * DIM) / 4) / 256, 256>>>(values, W);

    // VWt[d][n] = sum_k W[d,k] V[n,k]   (M=512, N=1024, K=512)
    k_gemm<512, 0><<<dim3(4, 8), 256, SMEM_SZ>>>(
        wb_p, vb_p, vwt_p, nullptr, nullptr, nullptr);

    // E = exp(score(X @ P^T)) + partial rowsums  (M=16384, N=1024, K=512)
    k_gemm<512, 1><<<dim3(128, 8), 256, SMEM_SZ>>>(
        xb_p, pb_p, E_p, xsq_p, psq_p, scales);

    k_rs_reduce<<<MTOT / 256, 256>>>();

    // out = E @ VWt^T / rowsum + b      (M=16384, N=512, K=1024)
    k_gemm<1024, 2><<<dim3(128, 4), 256, SMEM_SZ>>>(
        E_p, vwt_p, out, rs_p, b, nullptr);
}

// round 8
// speedup vs baseline: 1.4363x; 1.0494x over previous
#include <cuda_runtime.h>
#include <cuda_bf16.h>
#include <cstdint>

// ============================================================================
// CrystalAttention, sm_100-baseline ISA (mma.sync + cp.async; no tcgen05).
//   VWt[d][n] = sum_k W[d,k] V[n,k]
//   S = X @ P^T ; E = exp(scales/(sqrt(max(xsq+psq-2S,0))+0.1))
//   out = (E @ VWt^T) / rowsum(E) + b_out
// M=16384, D=512, N=1024.
// R8: same GEMM core as R7 (128x128 tile, 4x2 warps, 3-stage, 1 sync/chunk,
// 2 CTAs/SM). New: dual-stream overlap (conv+VWt || rowsq+scores),
// warp-per-row rowsq, rowsum reduce inlined into out-GEMM epilogue.
// ============================================================================
#define MTOT 16384
#define DIM  512
#define NNEU 1024

__device__ __nv_bfloat16 g_xb[(size_t)MTOT * DIM];
__device__ float         g_xsq[MTOT];
__device__ __nv_bfloat16 g_pb[(size_t)NNEU * DIM];
__device__ float         g_psq[NNEU];
__device__ __nv_bfloat16 g_vb[(size_t)NNEU * DIM];
__device__ __nv_bfloat16 g_wb[(size_t)DIM * DIM];
__device__ __nv_bfloat16 g_vwt[(size_t)DIM * NNEU];
__device__ __nv_bfloat16 g_E[(size_t)MTOT * NNEU];
__device__ float         g_rsp[(size_t)MTOT * 8];   // partial rowsums per nb

// ============================================================================
// helpers
// ============================================================================
__device__ __forceinline__ uint32_t smem_u32(const void* p) {
    uint32_t a;
    asm("{ .reg .u64 t; cvta.to.shared.u64 t, %1; cvt.u32.u64 %0, t; }"
        : "=r"(a) : "l"(p));
    return a;
}

#define CP_ASYNC16(saddr, gaddr) \
    asm volatile("cp.async.cg.shared.global [%0], [%1], 16;\n" \
                 :: "r"(saddr), "l"(gaddr) : "memory")
#define CP_COMMIT() asm volatile("cp.async.commit_group;\n" ::: "memory")
#define CP_WAIT(n)  asm volatile("cp.async.wait_group %0;\n" :: "n"(n) : "memory")

__device__ __forceinline__ void ldsm_x4(uint32_t* f, uint32_t addr) {
    asm volatile("ldmatrix.sync.aligned.m8n8.x4.shared.b16 {%0,%1,%2,%3}, [%4];\n"
                 : "=r"(f[0]), "=r"(f[1]), "=r"(f[2]), "=r"(f[3]) : "r"(addr));
}

__device__ __forceinline__ void mma16816(float* d, const uint32_t* a, const uint32_t* b) {
    asm volatile(
        "mma.sync.aligned.m16n8k16.row.col.f32.bf16.bf16.f32 "
        "{%0,%1,%2,%3}, {%4,%5,%6,%7}, {%8,%9}, {%0,%1,%2,%3};\n"
        : "+f"(d[0]), "+f"(d[1]), "+f"(d[2]), "+f"(d[3])
        : "r"(a[0]), "r"(a[1]), "r"(a[2]), "r"(a[3]), "r"(b[0]), "r"(b[1]));
}

// swizzled smem byte offset, 128B pitch rows, b16 col c (c%8==0)
__device__ __forceinline__ uint32_t sw_off(int r, int c) {
    return (uint32_t)(r * 128 + ((((c >> 3) ^ (r & 7))) << 4));
}

// ============================================================================
// prep: fp32->bf16 + row sum-of-squares. One warp per row, 4 float4 per lane.
// ============================================================================
__global__ void k_rowsq(const float* __restrict__ x, const float* __restrict__ pos) {
    int gw = blockIdx.x * 8 + (threadIdx.x >> 5);
    int lane = threadIdx.x & 31;
    const float* src;
    __nv_bfloat16* dstB;
    float* dstS;
    int r;
    if (gw < MTOT) { src = x;   dstB = g_xb; dstS = g_xsq; r = gw; }
    else           { src = pos; dstB = g_pb; dstS = g_psq; r = gw - MTOT; }

    const float4* p = reinterpret_cast<const float4*>(src) + (size_t)r * (DIM / 4);
    uint2* q = reinterpret_cast<uint2*>(dstB) + (size_t)r * (DIM / 4);
    float s = 0.f;
    #pragma unroll
    for (int i = 0; i < 4; i++) {
        float4 v = p[lane + 32 * i];
        __nv_bfloat162 p0 = __floats2bfloat162_rn(v.x, v.y);
        __nv_bfloat162 p1 = __floats2bfloat162_rn(v.z, v.w);
        uint2 u;
        u.x = *reinterpret_cast<uint32_t*>(&p0);
        u.y = *reinterpret_cast<uint32_t*>(&p1);
        q[lane + 32 * i] = u;
        s += v.x * v.x + v.y * v.y + v.z * v.z + v.w * v.w;
    }
    #pragma unroll
    for (int off = 16; off > 0; off >>= 1)
        s += __shfl_xor_sync(0xffffffffu, s, off);
    if (lane == 0) dstS[r] = s;
}

// prep: fp32->bf16 for values then W_out, one grid
__global__ void k_conv(const float* __restrict__ values, const float* __restrict__ W) {
    constexpr int NV4 = (NNEU * DIM) / 4;   // 131072
    int i = blockIdx.x * blockDim.x + threadIdx.x;
    const float* src;
    __nv_bfloat16* dst;
    int j;
    if (i < NV4) { src = values; dst = g_vb; j = i; }
    else         { src = W;      dst = g_wb; j = i - NV4; }
    float4 v = reinterpret_cast<const float4*>(src)[j];
    __nv_bfloat162 p0 = __floats2bfloat162_rn(v.x, v.y);
    __nv_bfloat162 p1 = __floats2bfloat162_rn(v.z, v.w);
    uint2 u;
    u.x = *reinterpret_cast<uint32_t*>(&p0);
    u.y = *reinterpret_cast<uint32_t*>(&p1);
    reinterpret_cast<uint2*>(dst)[j] = u;
}

// ============================================================================
// GEMM: C = A @ B^T. CTA tile 128(M) x 128(N), K chunk 64, 3-stage cp.async,
// single __syncthreads per chunk. 256 threads: warpM = wid>>1 (4),
// warpN = wid&1 (2); warp tile 32x64.
// MODE 0: bf16 store (VWt)    MODE 1: E=exp(score), bf16 + partial rowsum
// MODE 2: out = acc/rowsum(8 partials inline) + b, fp32
// ============================================================================
constexpr int STG    = 32768;            // bytes per stage (A 16KB + B 16KB)
constexpr int SM_RS  = 3 * STG;          // rowsum scratch (128*2 floats)
constexpr int SMEM_SZ = SM_RS + 1024;

template<int KTOT, int MODE>
__global__ void __launch_bounds__(256, 2) k_gemm(
    const __nv_bfloat16* __restrict__ Ag,
    const __nv_bfloat16* __restrict__ Bg,
    void* __restrict__ dst,
    const float* __restrict__ aux0,   // xsq (M1) / rsp partials (M2)
    const float* __restrict__ aux1,   // psq (M1) / bout  (M2)
    const float* __restrict__ aux2)   // scales (M1)
{
    constexpr int NC = KTOT / 64;
    extern __shared__ char smem[];
    const uint32_t sbase = smem_u32(smem);

    const int tid = threadIdx.x;
    const int lane = tid & 31, wid = tid >> 5;
    const int warpM = wid >> 1, warpN = wid & 1;
    const int m0 = blockIdx.x * 128;
    const int n0 = blockIdx.y * 128;

    auto prefetch = [&](int kc) {
        const __nv_bfloat16* Ab = Ag + (size_t)m0 * KTOT + kc * 64;
        const __nv_bfloat16* Bb = Bg + (size_t)n0 * KTOT + kc * 64;
        uint32_t da = sbase + (kc % 3) * STG;
        uint32_t db = da + 16384;
        #pragma unroll
        for (int it = 0; it < 4; it++) {          // A: 128 rows x 8 chunks
            int i = tid + it * 256;
            int r = i >> 3, ch = i & 7;
            CP_ASYNC16(da + sw_off(r, ch * 8), Ab + (size_t)r * KTOT + ch * 8);
        }
        #pragma unroll
        for (int it = 0; it < 4; it++) {          // B: 128 rows x 8 chunks
            int i = tid + it * 256;
            int r = i >> 3, ch = i & 7;
            CP_ASYNC16(db + sw_off(r, ch * 8), Bb + (size_t)r * KTOT + ch * 8);
        }
        CP_COMMIT();
    };

    float acc[2][8][4];
    #pragma unroll
    for (int i = 0; i < 2; i++)
        #pragma unroll
        for (int j = 0; j < 8; j++)
            #pragma unroll
            for (int k = 0; k < 4; k++) acc[i][j][k] = 0.f;

    prefetch(0);
    prefetch(1);

    for (int c = 0; c < NC; c++) {
        if (c + 1 < NC) CP_WAIT(1);
        else            CP_WAIT(0);
        __syncthreads();
        // Safe: the sync above proves every warp finished chunk c-1, whose
        // buffer (c-1)%3 == (c+2)%3 is exactly the prefetch target.
        if (c + 2 < NC) prefetch(c + 2);

        uint32_t sa = sbase + (c % 3) * STG;
        uint32_t sb = sa + 16384;

        #pragma unroll
        for (int ks = 0; ks < 4; ks++) {
            uint32_t af[2][4], bfr[8][2];
            #pragma unroll
            for (int mi = 0; mi < 2; mi++) {
                int r = warpM * 32 + mi * 16 + (lane & 15);
                int cc = ks * 16 + ((lane >> 4) << 3);
                ldsm_x4(af[mi], sa + sw_off(r, cc));
            }
            #pragma unroll
            for (int nb = 0; nb < 4; nb++) {
                int r = warpN * 64 + nb * 16 + ((lane >> 4) << 3) + (lane & 7);
                int cc = ks * 16 + (((lane >> 3) & 1) << 3);
                uint32_t f[4];
                ldsm_x4(f, sb + sw_off(r, cc));
                bfr[2 * nb][0] = f[0]; bfr[2 * nb][1] = f[1];
                bfr[2 * nb + 1][0] = f[2]; bfr[2 * nb + 1][1] = f[3];
            }
            #pragma unroll
            for (int mi = 0; mi < 2; mi++)
                #pragma unroll
                for (int nj = 0; nj < 8; nj++)
                    mma16816(acc[mi][nj], af[mi], bfr[nj]);
        }
    }
    __syncthreads();

    // ---- epilogue ----
    const int rb = lane >> 2;
    const int cb = (lane & 3) * 2;
    float* rs_sm = reinterpret_cast<float*>(smem + SM_RS);

    #pragma unroll
    for (int mi = 0; mi < 2; mi++) {
        int rt0 = warpM * 32 + mi * 16 + rb;       // row in tile; +8 for second
        int r0 = m0 + rt0;
        float rs0 = 0.f, rs1 = 0.f;
        float iv0 = 0.f, iv1 = 0.f;
        if (MODE == 2) {
            // inline rowsum: 8 partials per row
            float4 a0 = *reinterpret_cast<const float4*>(aux0 + (size_t)r0 * 8);
            float4 a1 = *reinterpret_cast<const float4*>(aux0 + (size_t)r0 * 8 + 4);
            float4 b0 = *reinterpret_cast<const float4*>(aux0 + (size_t)(r0 + 8) * 8);
            float4 b1 = *reinterpret_cast<const float4*>(aux0 + (size_t)(r0 + 8) * 8 + 4);
            iv0 = 1.f / ((a0.x + a0.y + a0.z + a0.w) + (a1.x + a1.y + a1.z + a1.w));
            iv1 = 1.f / ((b0.x + b0.y + b0.z + b0.w) + (b1.x + b1.y + b1.z + b1.w));
        }
        #pragma unroll
        for (int nj = 0; nj < 8; nj++) {
            int c0 = n0 + warpN * 64 + nj * 8 + cb;
            float* a = acc[mi][nj];
            if (MODE == 0) {
                __nv_bfloat16* D = (__nv_bfloat16*)dst;
                *reinterpret_cast<__nv_bfloat162*>(D + (size_t)r0 * NNEU + c0) =
                    __floats2bfloat162_rn(a[0], a[1]);
                *reinterpret_cast<__nv_bfloat162*>(D + (size_t)(r0 + 8) * NNEU + c0) =
                    __floats2bfloat162_rn(a[2], a[3]);
            } else if (MODE == 1) {
                __nv_bfloat16* D = (__nv_bfloat16*)dst;
                float xs0 = aux0[r0], xs1 = aux0[r0 + 8];
                float pq0 = aux1[c0], pq1 = aux1[c0 + 1];
                float sc0 = aux2[c0], sc1 = aux2[c0 + 1];
                float d00 = sqrtf(fmaxf(xs0 + pq0 - 2.f * a[0], 0.f));
                float d01 = sqrtf(fmaxf(xs0 + pq1 - 2.f * a[1], 0.f));
                float d10 = sqrtf(fmaxf(xs1 + pq0 - 2.f * a[2], 0.f));
                float d11 = sqrtf(fmaxf(xs1 + pq1 - 2.f * a[3], 0.f));
                float e00 = __expf(sc0 / (d00 + 0.1f));
                float e01 = __expf(sc1 / (d01 + 0.1f));
                float e10 = __expf(sc0 / (d10 + 0.1f));
                float e11 = __expf(sc1 / (d11 + 0.1f));
                rs0 += e00 + e01;
                rs1 += e10 + e11;
                *reinterpret_cast<__nv_bfloat162*>(D + (size_t)r0 * NNEU + c0) =
                    __floats2bfloat162_rn(e00, e01);
                *reinterpret_cast<__nv_bfloat162*>(D + (size_t)(r0 + 8) * NNEU + c0) =
                    __floats2bfloat162_rn(e10, e11);
            } else {
                float* D = (float*)dst;
                float b0 = aux1[c0], b1 = aux1[c0 + 1];
                float2 o0 = make_float2(a[0] * iv0 + b0, a[1] * iv0 + b1);
                float2 o1 = make_float2(a[2] * iv1 + b0, a[3] * iv1 + b1);
                *reinterpret_cast<float2*>(D + (size_t)r0 * DIM + c0) = o0;
                *reinterpret_cast<float2*>(D + (size_t)(r0 + 8) * DIM + c0) = o1;
            }
        }
        if (MODE == 1) {
            // reduce over the 4 lanes of the quad (cols), leave on lane&3==0
            rs0 += __shfl_xor_sync(0xffffffffu, rs0, 1);
            rs0 += __shfl_xor_sync(0xffffffffu, rs0, 2);
            rs1 += __shfl_xor_sync(0xffffffffu, rs1, 1);
            rs1 += __shfl_xor_sync(0xffffffffu, rs1, 2);
            if ((lane & 3) == 0) {
                rs_sm[rt0 * 2 + warpN] = rs0;
                rs_sm[(rt0 + 8) * 2 + warpN] = rs1;
            }
        }
    }
    if (MODE == 1) {
        __syncthreads();
        if (tid < 128) {
            float2 v = reinterpret_cast<const float2*>(rs_sm)[tid];
            g_rsp[(size_t)(m0 + tid) * 8 + blockIdx.y] = v.x + v.y;
        }
    }
}

// ============================================================================
// Host launcher — fork/join second stream for conv+VWt overlap with
// rowsq+scores. Stream/events created on first (uncaptured) call only.
// ============================================================================
extern "C" void kernel_launch(void* const* d_in, const int* in_sizes, int n_in,
                              void* d_out, int out_size) {
    (void)in_sizes; (void)n_in; (void)out_size;
    const float* x      = (const float*)d_in[0];
    const float* pos    = (const float*)d_in[1];
    const float* scales = (const float*)d_in[2];
    const float* values = (const float*)d_in[3];
    const float* W      = (const float*)d_in[4];
    const float* b      = (const float*)d_in[5];
    float* out = (float*)d_out;

    static __nv_bfloat16* vwt_p = nullptr;
    static __nv_bfloat16* E_p   = nullptr;
    static float *xsq_p, *psq_p, *rsp_p;
    static __nv_bfloat16 *xb_p, *pb_p, *vb_p, *wb_p;
    static cudaStream_t s2;
    static cudaEvent_t eFork, eJoin;
    if (!vwt_p) {
        cudaGetSymbolAddress((void**)&vwt_p, g_vwt);
        cudaGetSymbolAddress((void**)&E_p,   g_E);
        cudaGetSymbolAddress((void**)&xsq_p, g_xsq);
        cudaGetSymbolAddress((void**)&psq_p, g_psq);
        cudaGetSymbolAddress((void**)&rsp_p, g_rsp);
        cudaGetSymbolAddress((void**)&xb_p,  g_xb);
        cudaGetSymbolAddress((void**)&pb_p,  g_pb);
        cudaGetSymbolAddress((void**)&vb_p,  g_vb);
        cudaGetSymbolAddress((void**)&wb_p,  g_wb);
        cudaStreamCreateWithFlags(&s2, cudaStreamNonBlocking);
        cudaEventCreateWithFlags(&eFork, cudaEventDisableTiming);
        cudaEventCreateWithFlags(&eJoin, cudaEventDisableTiming);
        cudaFuncSetAttribute(k_gemm<512, 0>,
            cudaFuncAttributeMaxDynamicSharedMemorySize, SMEM_SZ);
        cudaFuncSetAttribute(k_gemm<512, 1>,
            cudaFuncAttributeMaxDynamicSharedMemorySize, SMEM_SZ);
        cudaFuncSetAttribute(k_gemm<1024, 2>,
            cudaFuncAttributeMaxDynamicSharedMemorySize, SMEM_SZ);
    }

    // fork side stream: conv -> VWt GEMM (independent of x path)
    cudaEventRecord(eFork, 0);
    cudaStreamWaitEvent(s2, eFork, 0);
    k_conv<<<((NNEU * DIM + DIM * DIM) / 4) / 256, 256, 0, s2>>>(values, W);
    k_gemm<512, 0><<<dim3(4, 8), 256, SMEM_SZ, s2>>>(
        wb_p, vb_p, vwt_p, nullptr, nullptr, nullptr);
    cudaEventRecord(eJoin, s2);

    // main stream: rowsq -> scores
    k_rowsq<<<(MTOT + NNEU) / 8, 256>>>(x, pos);
    k_gemm<512, 1><<<dim3(128, 8), 256, SMEM_SZ>>>(
        xb_p, pb_p, E_p, xsq_p, psq_p, scales);

    // join, then out = E @ VWt^T / rowsum + b   (rowsum inlined from g_rsp)
    cudaStreamWaitEvent(0, eJoin, 0);
    k_gemm<1024, 2><<<dim3(128, 4), 256, SMEM_SZ>>>(
        E_p, vwt_p, out, rsp_p, b, nullptr);
}

// round 9
// speedup vs baseline: 1.4914x; 1.0383x over previous
#include <cuda_runtime.h>
#include <cuda_bf16.h>
#include <cstdint>

// ============================================================================
// CrystalAttention, sm_100-baseline ISA (mma.sync + cp.async; no tcgen05).
//   VWt[d][n] = sum_k W[d,k] V[n,k]
//   S = X @ P^T ; E = exp(scales/(sqrt(max(xsq+psq-2S,0))+0.1))
//   out = (E @ VWt^T) / rowsum(E) + b_out
// M=16384, D=512, N=1024.
// R9: CTA tile 128x64, warp tile 32x32 (4x2 warps), 3-stage, 1 sync/chunk,
// 3 CTAs/SM (24 warps) — trade acc registers for warp-level parallelism.
// ============================================================================
#define MTOT 16384
#define DIM  512
#define NNEU 1024

__device__ __nv_bfloat16 g_xb[(size_t)MTOT * DIM];
__device__ float         g_xsq[MTOT];
__device__ __nv_bfloat16 g_pb[(size_t)NNEU * DIM];
__device__ float         g_psq[NNEU];
__device__ __nv_bfloat16 g_vb[(size_t)NNEU * DIM];
__device__ __nv_bfloat16 g_wb[(size_t)DIM * DIM];
__device__ __nv_bfloat16 g_vwt[(size_t)DIM * NNEU];
__device__ __nv_bfloat16 g_E[(size_t)MTOT * NNEU];
__device__ float         g_rsp[(size_t)MTOT * 16];  // partial rowsums per nb

// ============================================================================
// helpers
// ============================================================================
__device__ __forceinline__ uint32_t smem_u32(const void* p) {
    uint32_t a;
    asm("{ .reg .u64 t; cvta.to.shared.u64 t, %1; cvt.u32.u64 %0, t; }"
        : "=r"(a) : "l"(p));
    return a;
}

#define CP_ASYNC16(saddr, gaddr) \
    asm volatile("cp.async.cg.shared.global [%0], [%1], 16;\n" \
                 :: "r"(saddr), "l"(gaddr) : "memory")
#define CP_COMMIT() asm volatile("cp.async.commit_group;\n" ::: "memory")
#define CP_WAIT(n)  asm volatile("cp.async.wait_group %0;\n" :: "n"(n) : "memory")

__device__ __forceinline__ void ldsm_x4(uint32_t* f, uint32_t addr) {
    asm volatile("ldmatrix.sync.aligned.m8n8.x4.shared.b16 {%0,%1,%2,%3}, [%4];\n"
                 : "=r"(f[0]), "=r"(f[1]), "=r"(f[2]), "=r"(f[3]) : "r"(addr));
}

__device__ __forceinline__ void mma16816(float* d, const uint32_t* a, const uint32_t* b) {
    asm volatile(
        "mma.sync.aligned.m16n8k16.row.col.f32.bf16.bf16.f32 "
        "{%0,%1,%2,%3}, {%4,%5,%6,%7}, {%8,%9}, {%0,%1,%2,%3};\n"
        : "+f"(d[0]), "+f"(d[1]), "+f"(d[2]), "+f"(d[3])
        : "r"(a[0]), "r"(a[1]), "r"(a[2]), "r"(a[3]), "r"(b[0]), "r"(b[1]));
}

// swizzled smem byte offset, 128B pitch rows, b16 col c (c%8==0)
__device__ __forceinline__ uint32_t sw_off(int r, int c) {
    return (uint32_t)(r * 128 + ((((c >> 3) ^ (r & 7))) << 4));
}

// ============================================================================
// prep: fp32->bf16 + row sum-of-squares. One warp per row, 4 float4 per lane.
// ============================================================================
__global__ void k_rowsq(const float* __restrict__ x, const float* __restrict__ pos) {
    int gw = blockIdx.x * 8 + (threadIdx.x >> 5);
    int lane = threadIdx.x & 31;
    const float* src;
    __nv_bfloat16* dstB;
    float* dstS;
    int r;
    if (gw < MTOT) { src = x;   dstB = g_xb; dstS = g_xsq; r = gw; }
    else           { src = pos; dstB = g_pb; dstS = g_psq; r = gw - MTOT; }

    const float4* p = reinterpret_cast<const float4*>(src) + (size_t)r * (DIM / 4);
    uint2* q = reinterpret_cast<uint2*>(dstB) + (size_t)r * (DIM / 4);
    float s = 0.f;
    #pragma unroll
    for (int i = 0; i < 4; i++) {
        float4 v = p[lane + 32 * i];
        __nv_bfloat162 p0 = __floats2bfloat162_rn(v.x, v.y);
        __nv_bfloat162 p1 = __floats2bfloat162_rn(v.z, v.w);
        uint2 u;
        u.x = *reinterpret_cast<uint32_t*>(&p0);
        u.y = *reinterpret_cast<uint32_t*>(&p1);
        q[lane + 32 * i] = u;
        s += v.x * v.x + v.y * v.y + v.z * v.z + v.w * v.w;
    }
    #pragma unroll
    for (int off = 16; off > 0; off >>= 1)
        s += __shfl_xor_sync(0xffffffffu, s, off);
    if (lane == 0) dstS[r] = s;
}

// prep: fp32->bf16 for values then W_out, one grid
__global__ void k_conv(const float* __restrict__ values, const float* __restrict__ W) {
    constexpr int NV4 = (NNEU * DIM) / 4;   // 131072
    int i = blockIdx.x * blockDim.x + threadIdx.x;
    const float* src;
    __nv_bfloat16* dst;
    int j;
    if (i < NV4) { src = values; dst = g_vb; j = i; }
    else         { src = W;      dst = g_wb; j = i - NV4; }
    float4 v = reinterpret_cast<const float4*>(src)[j];
    __nv_bfloat162 p0 = __floats2bfloat162_rn(v.x, v.y);
    __nv_bfloat162 p1 = __floats2bfloat162_rn(v.z, v.w);
    uint2 u;
    u.x = *reinterpret_cast<uint32_t*>(&p0);
    u.y = *reinterpret_cast<uint32_t*>(&p1);
    reinterpret_cast<uint2*>(dst)[j] = u;
}

// ============================================================================
// GEMM: C = A @ B^T. CTA tile 128(M) x 64(N), K chunk 64, 3-stage cp.async,
// single __syncthreads per chunk. 256 threads: warpM = wid>>1 (4),
// warpN = wid&1 (2); warp tile 32x32. 3 CTAs/SM.
// MODE 0: bf16 store (VWt)    MODE 1: E=exp(score), bf16 + partial rowsum
// MODE 2: out = acc/rowsum(16 partials inline) + b, fp32
// ============================================================================
constexpr int STG    = 24576;            // bytes per stage (A 16KB + B 8KB)
constexpr int SM_RS  = 3 * STG;          // rowsum scratch (128*2 floats)
constexpr int SMEM_SZ = SM_RS + 1024;    // 74752 B/CTA; 3 CTAs = 219 KB

template<int KTOT, int MODE>
__global__ void __launch_bounds__(256, 3) k_gemm(
    const __nv_bfloat16* __restrict__ Ag,
    const __nv_bfloat16* __restrict__ Bg,
    void* __restrict__ dst,
    const float* __restrict__ aux0,   // xsq (M1) / rsp partials (M2)
    const float* __restrict__ aux1,   // psq (M1) / bout  (M2)
    const float* __restrict__ aux2)   // scales (M1)
{
    constexpr int NC = KTOT / 64;
    extern __shared__ char smem[];
    const uint32_t sbase = smem_u32(smem);

    const int tid = threadIdx.x;
    const int lane = tid & 31, wid = tid >> 5;
    const int warpM = wid >> 1, warpN = wid & 1;
    const int m0 = blockIdx.x * 128;
    const int n0 = blockIdx.y * 64;

    auto prefetch = [&](int kc) {
        const __nv_bfloat16* Ab = Ag + (size_t)m0 * KTOT + kc * 64;
        const __nv_bfloat16* Bb = Bg + (size_t)n0 * KTOT + kc * 64;
        uint32_t da = sbase + (kc % 3) * STG;
        uint32_t db = da + 16384;
        #pragma unroll
        for (int it = 0; it < 4; it++) {          // A: 128 rows x 8 chunks
            int i = tid + it * 256;
            int r = i >> 3, ch = i & 7;
            CP_ASYNC16(da + sw_off(r, ch * 8), Ab + (size_t)r * KTOT + ch * 8);
        }
        #pragma unroll
        for (int it = 0; it < 2; it++) {          // B: 64 rows x 8 chunks
            int i = tid + it * 256;
            int r = i >> 3, ch = i & 7;
            CP_ASYNC16(db + sw_off(r, ch * 8), Bb + (size_t)r * KTOT + ch * 8);
        }
        CP_COMMIT();
    };

    float acc[2][4][4];
    #pragma unroll
    for (int i = 0; i < 2; i++)
        #pragma unroll
        for (int j = 0; j < 4; j++)
            #pragma unroll
            for (int k = 0; k < 4; k++) acc[i][j][k] = 0.f;

    prefetch(0);
    prefetch(1);

    for (int c = 0; c < NC; c++) {
        if (c + 1 < NC) CP_WAIT(1);
        else            CP_WAIT(0);
        __syncthreads();
        // Safe: the sync above proves every warp finished chunk c-1, whose
        // buffer (c-1)%3 == (c+2)%3 is exactly the prefetch target.
        if (c + 2 < NC) prefetch(c + 2);

        uint32_t sa = sbase + (c % 3) * STG;
        uint32_t sb = sa + 16384;

        #pragma unroll
        for (int ks = 0; ks < 4; ks++) {
            uint32_t af[2][4], bfr[4][2];
            #pragma unroll
            for (int mi = 0; mi < 2; mi++) {
                int r = warpM * 32 + mi * 16 + (lane & 15);
                int cc = ks * 16 + ((lane >> 4) << 3);
                ldsm_x4(af[mi], sa + sw_off(r, cc));
            }
            #pragma unroll
            for (int nb = 0; nb < 2; nb++) {
                int r = warpN * 32 + nb * 16 + ((lane >> 4) << 3) + (lane & 7);
                int cc = ks * 16 + (((lane >> 3) & 1) << 3);
                uint32_t f[4];
                ldsm_x4(f, sb + sw_off(r, cc));
                bfr[2 * nb][0] = f[0]; bfr[2 * nb][1] = f[1];
                bfr[2 * nb + 1][0] = f[2]; bfr[2 * nb + 1][1] = f[3];
            }
            #pragma unroll
            for (int mi = 0; mi < 2; mi++)
                #pragma unroll
                for (int nj = 0; nj < 4; nj++)
                    mma16816(acc[mi][nj], af[mi], bfr[nj]);
        }
    }
    __syncthreads();

    // ---- epilogue ----
    const int rb = lane >> 2;
    const int cb = (lane & 3) * 2;
    float* rs_sm = reinterpret_cast<float*>(smem + SM_RS);

    #pragma unroll
    for (int mi = 0; mi < 2; mi++) {
        int rt0 = warpM * 32 + mi * 16 + rb;       // row in tile; +8 for second
        int r0 = m0 + rt0;
        float rs0 = 0.f, rs1 = 0.f;
        float iv0 = 0.f, iv1 = 0.f;
        if (MODE == 2) {
            // inline rowsum: 16 partials per row
            float s0 = 0.f, s1 = 0.f;
            #pragma unroll
            for (int q = 0; q < 4; q++) {
                float4 a = *reinterpret_cast<const float4*>(
                    aux0 + (size_t)r0 * 16 + q * 4);
                float4 b = *reinterpret_cast<const float4*>(
                    aux0 + (size_t)(r0 + 8) * 16 + q * 4);
                s0 += (a.x + a.y) + (a.z + a.w);
                s1 += (b.x + b.y) + (b.z + b.w);
            }
            iv0 = 1.f / s0;
            iv1 = 1.f / s1;
        }
        #pragma unroll
        for (int nj = 0; nj < 4; nj++) {
            int c0 = n0 + warpN * 32 + nj * 8 + cb;
            float* a = acc[mi][nj];
            if (MODE == 0) {
                __nv_bfloat16* D = (__nv_bfloat16*)dst;
                *reinterpret_cast<__nv_bfloat162*>(D + (size_t)r0 * NNEU + c0) =
                    __floats2bfloat162_rn(a[0], a[1]);
                *reinterpret_cast<__nv_bfloat162*>(D + (size_t)(r0 + 8) * NNEU + c0) =
                    __floats2bfloat162_rn(a[2], a[3]);
            } else if (MODE == 1) {
                __nv_bfloat16* D = (__nv_bfloat16*)dst;
                float xs0 = aux0[r0], xs1 = aux0[r0 + 8];
                float pq0 = aux1[c0], pq1 = aux1[c0 + 1];
                float sc0 = aux2[c0], sc1 = aux2[c0 + 1];
                float d00 = sqrtf(fmaxf(xs0 + pq0 - 2.f * a[0], 0.f));
                float d01 = sqrtf(fmaxf(xs0 + pq1 - 2.f * a[1], 0.f));
                float d10 = sqrtf(fmaxf(xs1 + pq0 - 2.f * a[2], 0.f));
                float d11 = sqrtf(fmaxf(xs1 + pq1 - 2.f * a[3], 0.f));
                float e00 = __expf(sc0 / (d00 + 0.1f));
                float e01 = __expf(sc1 / (d01 + 0.1f));
                float e10 = __expf(sc0 / (d10 + 0.1f));
                float e11 = __expf(sc1 / (d11 + 0.1f));
                rs0 += e00 + e01;
                rs1 += e10 + e11;
                *reinterpret_cast<__nv_bfloat162*>(D + (size_t)r0 * NNEU + c0) =
                    __floats2bfloat162_rn(e00, e01);
                *reinterpret_cast<__nv_bfloat162*>(D + (size_t)(r0 + 8) * NNEU + c0) =
                    __floats2bfloat162_rn(e10, e11);
            } else {
                float* D = (float*)dst;
                float b0 = aux1[c0], b1 = aux1[c0 + 1];
                float2 o0 = make_float2(a[0] * iv0 + b0, a[1] * iv0 + b1);
                float2 o1 = make_float2(a[2] * iv1 + b0, a[3] * iv1 + b1);
                *reinterpret_cast<float2*>(D + (size_t)r0 * DIM + c0) = o0;
                *reinterpret_cast<float2*>(D + (size_t)(r0 + 8) * DIM + c0) = o1;
            }
        }
        if (MODE == 1) {
            // reduce over the 4 lanes of the quad (cols), leave on lane&3==0
            rs0 += __shfl_xor_sync(0xffffffffu, rs0, 1);
            rs0 += __shfl_xor_sync(0xffffffffu, rs0, 2);
            rs1 += __shfl_xor_sync(0xffffffffu, rs1, 1);
            rs1 += __shfl_xor_sync(0xffffffffu, rs1, 2);
            if ((lane & 3) == 0) {
                rs_sm[rt0 * 2 + warpN] = rs0;
                rs_sm[(rt0 + 8) * 2 + warpN] = rs1;
            }
        }
    }
    if (MODE == 1) {
        __syncthreads();
        if (tid < 128) {
            float2 v = reinterpret_cast<const float2*>(rs_sm)[tid];
            g_rsp[(size_t)(m0 + tid) * 16 + blockIdx.y] = v.x + v.y;
        }
    }
}

// ============================================================================
// Host launcher — fork/join second stream for conv+VWt overlap with
// rowsq+scores. Stream/events created on first (uncaptured) call only.
// ============================================================================
extern "C" void kernel_launch(void* const* d_in, const int* in_sizes, int n_in,
                              void* d_out, int out_size) {
    (void)in_sizes; (void)n_in; (void)out_size;
    const float* x      = (const float*)d_in[0];
    const float* pos    = (const float*)d_in[1];
    const float* scales = (const float*)d_in[2];
    const float* values = (const float*)d_in[3];
    const float* W      = (const float*)d_in[4];
    const float* b      = (const float*)d_in[5];
    float* out = (float*)d_out;

    static __nv_bfloat16* vwt_p = nullptr;
    static __nv_bfloat16* E_p   = nullptr;
    static float *xsq_p, *psq_p, *rsp_p;
    static __nv_bfloat16 *xb_p, *pb_p, *vb_p, *wb_p;
    static cudaStream_t s2;
    static cudaEvent_t eFork, eJoin;
    if (!vwt_p) {
        cudaGetSymbolAddress((void**)&vwt_p, g_vwt);
        cudaGetSymbolAddress((void**)&E_p,   g_E);
        cudaGetSymbolAddress((void**)&xsq_p, g_xsq);
        cudaGetSymbolAddress((void**)&psq_p, g_psq);
        cudaGetSymbolAddress((void**)&rsp_p, g_rsp);
        cudaGetSymbolAddress((void**)&xb_p,  g_xb);
        cudaGetSymbolAddress((void**)&pb_p,  g_pb);
        cudaGetSymbolAddress((void**)&vb_p,  g_vb);
        cudaGetSymbolAddress((void**)&wb_p,  g_wb);
        cudaStreamCreateWithFlags(&s2, cudaStreamNonBlocking);
        cudaEventCreateWithFlags(&eFork, cudaEventDisableTiming);
        cudaEventCreateWithFlags(&eJoin, cudaEventDisableTiming);
        cudaFuncSetAttribute(k_gemm<512, 0>,
            cudaFuncAttributeMaxDynamicSharedMemorySize, SMEM_SZ);
        cudaFuncSetAttribute(k_gemm<512, 1>,
            cudaFuncAttributeMaxDynamicSharedMemorySize, SMEM_SZ);
        cudaFuncSetAttribute(k_gemm<1024, 2>,
            cudaFuncAttributeMaxDynamicSharedMemorySize, SMEM_SZ);
    }

    // fork side stream: conv -> VWt GEMM (independent of x path)
    cudaEventRecord(eFork, 0);
    cudaStreamWaitEvent(s2, eFork, 0);
    k_conv<<<((NNEU * DIM + DIM * DIM) / 4) / 256, 256, 0, s2>>>(values, W);
    k_gemm<512, 0><<<dim3(4, 16), 256, SMEM_SZ, s2>>>(
        wb_p, vb_p, vwt_p, nullptr, nullptr, nullptr);
    cudaEventRecord(eJoin, s2);

    // main stream: rowsq -> scores
    k_rowsq<<<(MTOT + NNEU) / 8, 256>>>(x, pos);
    k_gemm<512, 1><<<dim3(128, 16), 256, SMEM_SZ>>>(
        xb_p, pb_p, E_p, xsq_p, psq_p, scales);

    // join, then out = E @ VWt^T / rowsum + b   (rowsum inlined from g_rsp)
    cudaStreamWaitEvent(0, eJoin, 0);
    k_gemm<1024, 2><<<dim3(128, 8), 256, SMEM_SZ>>>(
        E_p, vwt_p, out, rsp_p, b, nullptr);
}

// round 11
// speedup vs baseline: 1.5486x; 1.0384x over previous
#include <cuda_runtime.h>
#include <cuda_fp16.h>
#include <cstdint>

// ============================================================================
// CrystalAttention, sm_100-baseline ISA (mma.sync + cp.async; no tcgen05).
//   VWt[d][n] = sum_k W[d,k] V[n,k]
//   S = X @ P^T ; E = exp(scales/(sqrt(max(xsq+psq-2S,0))+0.1))
//   out = (E @ VWt^T) / rowsum(E) + b_out
// M=16384, D=512, N=1024.
// R11: R10 (fp16 pipeline, f16-accum mma, 128x128 tile, 32x64 warp tile,
// 3 CTAs/SM) with the pipeline sync bug fixed: CP_WAIT -> barrier -> prefetch.
// ============================================================================
#define MTOT 16384
#define DIM  512
#define NNEU 1024

__device__ __half  g_xb[(size_t)MTOT * DIM];
__device__ float   g_xsq[MTOT];
__device__ __half  g_pb[(size_t)NNEU * DIM];
__device__ float   g_psq[NNEU];
__device__ __half  g_vb[(size_t)NNEU * DIM];
__device__ __half  g_wb[(size_t)DIM * DIM];
__device__ __half  g_vwt[(size_t)DIM * NNEU];
__device__ __half  g_E[(size_t)MTOT * NNEU];
__device__ float   g_rsp[(size_t)MTOT * 8];   // partial rowsums per nb

// ============================================================================
// helpers
// ============================================================================
__device__ __forceinline__ uint32_t smem_u32(const void* p) {
    uint32_t a;
    asm("{ .reg .u64 t; cvta.to.shared.u64 t, %1; cvt.u32.u64 %0, t; }"
        : "=r"(a) : "l"(p));
    return a;
}

#define CP_ASYNC16(saddr, gaddr) \
    asm volatile("cp.async.cg.shared.global [%0], [%1], 16;\n" \
                 :: "r"(saddr), "l"(gaddr) : "memory")
#define CP_COMMIT() asm volatile("cp.async.commit_group;\n" ::: "memory")
#define CP_WAIT(n)  asm volatile("cp.async.wait_group %0;\n" :: "n"(n) : "memory")

__device__ __forceinline__ void ldsm_x4(uint32_t* f, uint32_t addr) {
    asm volatile("ldmatrix.sync.aligned.m8n8.x4.shared.b16 {%0,%1,%2,%3}, [%4];\n"
                 : "=r"(f[0]), "=r"(f[1]), "=r"(f[2]), "=r"(f[3]) : "r"(addr));
}

// f16-accumulate MMA: D(f16x2 x2) = A(f16 x4) * B(f16 x2) + D
__device__ __forceinline__ void mma16816_f16(uint32_t* d, const uint32_t* a,
                                             const uint32_t* b) {
    asm volatile(
        "mma.sync.aligned.m16n8k16.row.col.f16.f16.f16.f16 "
        "{%0,%1}, {%2,%3,%4,%5}, {%6,%7}, {%0,%1};\n"
        : "+r"(d[0]), "+r"(d[1])
        : "r"(a[0]), "r"(a[1]), "r"(a[2]), "r"(a[3]), "r"(b[0]), "r"(b[1]));
}

// swizzled smem byte offset, 128B pitch rows, b16 col c (c%8==0)
__device__ __forceinline__ uint32_t sw_off(int r, int c) {
    return (uint32_t)(r * 128 + ((((c >> 3) ^ (r & 7))) << 4));
}

// ============================================================================
// prep: fp32->fp16 + row sum-of-squares. One warp per row, 4 float4 per lane.
// ============================================================================
__global__ void k_rowsq(const float* __restrict__ x, const float* __restrict__ pos) {
    int gw = blockIdx.x * 8 + (threadIdx.x >> 5);
    int lane = threadIdx.x & 31;
    const float* src;
    __half* dstB;
    float* dstS;
    int r;
    if (gw < MTOT) { src = x;   dstB = g_xb; dstS = g_xsq; r = gw; }
    else           { src = pos; dstB = g_pb; dstS = g_psq; r = gw - MTOT; }

    const float4* p = reinterpret_cast<const float4*>(src) + (size_t)r * (DIM / 4);
    uint2* q = reinterpret_cast<uint2*>(dstB) + (size_t)r * (DIM / 4);
    float s = 0.f;
    #pragma unroll
    for (int i = 0; i < 4; i++) {
        float4 v = p[lane + 32 * i];
        __half2 p0 = __floats2half2_rn(v.x, v.y);
        __half2 p1 = __floats2half2_rn(v.z, v.w);
        uint2 u;
        u.x = *reinterpret_cast<uint32_t*>(&p0);
        u.y = *reinterpret_cast<uint32_t*>(&p1);
        q[lane + 32 * i] = u;
        s += v.x * v.x + v.y * v.y + v.z * v.z + v.w * v.w;
    }
    #pragma unroll
    for (int off = 16; off > 0; off >>= 1)
        s += __shfl_xor_sync(0xffffffffu, s, off);
    if (lane == 0) dstS[r] = s;
}

// prep: fp32->fp16 for values then W_out, one grid
__global__ void k_conv(const float* __restrict__ values, const float* __restrict__ W) {
    constexpr int NV4 = (NNEU * DIM) / 4;   // 131072
    int i = blockIdx.x * blockDim.x + threadIdx.x;
    const float* src;
    __half* dst;
    int j;
    if (i < NV4) { src = values; dst = g_vb; j = i; }
    else         { src = W;      dst = g_wb; j = i - NV4; }
    float4 v = reinterpret_cast<const float4*>(src)[j];
    __half2 p0 = __floats2half2_rn(v.x, v.y);
    __half2 p1 = __floats2half2_rn(v.z, v.w);
    uint2 u;
    u.x = *reinterpret_cast<uint32_t*>(&p0);
    u.y = *reinterpret_cast<uint32_t*>(&p1);
    reinterpret_cast<uint2*>(dst)[j] = u;
}

// ============================================================================
// GEMM: C = A @ B^T. CTA tile 128(M) x 128(N), K chunk 64, 2-stage cp.async,
// single __syncthreads per chunk (wait -> barrier -> prefetch -> compute).
// 256 threads: warpM = wid>>1 (4), warpN = wid&1 (2); warp tile 32x64,
// f16 accumulators. 3 CTAs/SM.
// MODE 0: f16 store (VWt)     MODE 1: E=exp(score), f16 + partial rowsum
// MODE 2: out = acc/rowsum(8 partials inline) + b, fp32
// ============================================================================
constexpr int STG    = 32768;            // bytes per stage (A 16KB + B 16KB)
constexpr int SM_RS  = 2 * STG;          // rowsum scratch (128*2 floats)
constexpr int SMEM_SZ = SM_RS + 1024;    // 66560 B/CTA; 3 CTAs = 195 KB

template<int KTOT, int MODE>
__global__ void __launch_bounds__(256, 3) k_gemm(
    const __half* __restrict__ Ag,
    const __half* __restrict__ Bg,
    void* __restrict__ dst,
    const float* __restrict__ aux0,   // xsq (M1) / rsp partials (M2)
    const float* __restrict__ aux1,   // psq (M1) / bout  (M2)
    const float* __restrict__ aux2)   // scales (M1)
{
    constexpr int NC = KTOT / 64;
    extern __shared__ char smem[];
    const uint32_t sbase = smem_u32(smem);

    const int tid = threadIdx.x;
    const int lane = tid & 31, wid = tid >> 5;
    const int warpM = wid >> 1, warpN = wid & 1;
    const int m0 = blockIdx.x * 128;
    const int n0 = blockIdx.y * 128;

    auto prefetch = [&](int kc) {
        const __half* Ab = Ag + (size_t)m0 * KTOT + kc * 64;
        const __half* Bb = Bg + (size_t)n0 * KTOT + kc * 64;
        uint32_t da = sbase + (kc & 1) * STG;
        uint32_t db = da + 16384;
        #pragma unroll
        for (int it = 0; it < 4; it++) {          // A: 128 rows x 8 chunks
            int i = tid + it * 256;
            int r = i >> 3, ch = i & 7;
            CP_ASYNC16(da + sw_off(r, ch * 8), Ab + (size_t)r * KTOT + ch * 8);
        }
        #pragma unroll
        for (int it = 0; it < 4; it++) {          // B: 128 rows x 8 chunks
            int i = tid + it * 256;
            int r = i >> 3, ch = i & 7;
            CP_ASYNC16(db + sw_off(r, ch * 8), Bb + (size_t)r * KTOT + ch * 8);
        }
        CP_COMMIT();
    };

    uint32_t acc[2][8][2];    // f16x2 accumulators
    #pragma unroll
    for (int i = 0; i < 2; i++)
        #pragma unroll
        for (int j = 0; j < 8; j++) { acc[i][j][0] = 0u; acc[i][j][1] = 0u; }

    prefetch(0);

    for (int c = 0; c < NC; c++) {
        // Wait for own copies of chunk c, then barrier: makes all threads'
        // chunk-c data globally visible AND proves all warps finished
        // compute(c-1) -> buffer (c+1)&1 == (c-1)&1 is free for prefetch.
        CP_WAIT(0);
        __syncthreads();
        if (c + 1 < NC) prefetch(c + 1);

        uint32_t sa = sbase + (c & 1) * STG;
        uint32_t sb = sa + 16384;

        #pragma unroll
        for (int ks = 0; ks < 4; ks++) {
            uint32_t af[2][4], bfr[8][2];
            #pragma unroll
            for (int mi = 0; mi < 2; mi++) {
                int r = warpM * 32 + mi * 16 + (lane & 15);
                int cc = ks * 16 + ((lane >> 4) << 3);
                ldsm_x4(af[mi], sa + sw_off(r, cc));
            }
            #pragma unroll
            for (int nb = 0; nb < 4; nb++) {
                int r = warpN * 64 + nb * 16 + ((lane >> 4) << 3) + (lane & 7);
                int cc = ks * 16 + (((lane >> 3) & 1) << 3);
                uint32_t f[4];
                ldsm_x4(f, sb + sw_off(r, cc));
                bfr[2 * nb][0] = f[0]; bfr[2 * nb][1] = f[1];
                bfr[2 * nb + 1][0] = f[2]; bfr[2 * nb + 1][1] = f[3];
            }
            #pragma unroll
            for (int mi = 0; mi < 2; mi++)
                #pragma unroll
                for (int nj = 0; nj < 8; nj++)
                    mma16816_f16(acc[mi][nj], af[mi], bfr[nj]);
        }
    }
    __syncthreads();

    // ---- epilogue ----
    const int rb = lane >> 2;
    const int cb = (lane & 3) * 2;
    float* rs_sm = reinterpret_cast<float*>(smem + SM_RS);

    #pragma unroll
    for (int mi = 0; mi < 2; mi++) {
        int rt0 = warpM * 32 + mi * 16 + rb;       // row in tile; +8 for second
        int r0 = m0 + rt0;
        float rs0 = 0.f, rs1 = 0.f;
        float iv0 = 0.f, iv1 = 0.f;
        if (MODE == 2) {
            // inline rowsum: 8 partials per row
            float4 a0 = *reinterpret_cast<const float4*>(aux0 + (size_t)r0 * 8);
            float4 a1 = *reinterpret_cast<const float4*>(aux0 + (size_t)r0 * 8 + 4);
            float4 b0 = *reinterpret_cast<const float4*>(aux0 + (size_t)(r0 + 8) * 8);
            float4 b1 = *reinterpret_cast<const float4*>(aux0 + (size_t)(r0 + 8) * 8 + 4);
            iv0 = 1.f / ((a0.x + a0.y + a0.z + a0.w) + (a1.x + a1.y + a1.z + a1.w));
            iv1 = 1.f / ((b0.x + b0.y + b0.z + b0.w) + (b1.x + b1.y + b1.z + b1.w));
        }
        #pragma unroll
        for (int nj = 0; nj < 8; nj++) {
            int c0 = n0 + warpN * 64 + nj * 8 + cb;
            __half2 h0 = *reinterpret_cast<__half2*>(&acc[mi][nj][0]); // row r0
            __half2 h1 = *reinterpret_cast<__half2*>(&acc[mi][nj][1]); // row r0+8
            if (MODE == 0) {
                __half* D = (__half*)dst;
                *reinterpret_cast<__half2*>(D + (size_t)r0 * NNEU + c0) = h0;
                *reinterpret_cast<__half2*>(D + (size_t)(r0 + 8) * NNEU + c0) = h1;
            } else if (MODE == 1) {
                __half* D = (__half*)dst;
                float2 f0 = __half22float2(h0);
                float2 f1 = __half22float2(h1);
                float xs0 = aux0[r0], xs1 = aux0[r0 + 8];
                float pq0 = aux1[c0], pq1 = aux1[c0 + 1];
                float sc0 = aux2[c0], sc1 = aux2[c0 + 1];
                float d00 = sqrtf(fmaxf(xs0 + pq0 - 2.f * f0.x, 0.f));
                float d01 = sqrtf(fmaxf(xs0 + pq1 - 2.f * f0.y, 0.f));
                float d10 = sqrtf(fmaxf(xs1 + pq0 - 2.f * f1.x, 0.f));
                float d11 = sqrtf(fmaxf(xs1 + pq1 - 2.f * f1.y, 0.f));
                float e00 = __expf(sc0 / (d00 + 0.1f));
                float e01 = __expf(sc1 / (d01 + 0.1f));
                float e10 = __expf(sc0 / (d10 + 0.1f));
                float e11 = __expf(sc1 / (d11 + 0.1f));
                rs0 += e00 + e01;
                rs1 += e10 + e11;
                *reinterpret_cast<__half2*>(D + (size_t)r0 * NNEU + c0) =
                    __floats2half2_rn(e00, e01);
                *reinterpret_cast<__half2*>(D + (size_t)(r0 + 8) * NNEU + c0) =
                    __floats2half2_rn(e10, e11);
            } else {
                float* D = (float*)dst;
                float2 f0 = __half22float2(h0);
                float2 f1 = __half22float2(h1);
                float b0 = aux1[c0], b1 = aux1[c0 + 1];
                float2 o0 = make_float2(f0.x * iv0 + b0, f0.y * iv0 + b1);
                float2 o1 = make_float2(f1.x * iv1 + b0, f1.y * iv1 + b1);
                *reinterpret_cast<float2*>(D + (size_t)r0 * DIM + c0) = o0;
                *reinterpret_cast<float2*>(D + (size_t)(r0 + 8) * DIM + c0) = o1;
            }
        }
        if (MODE == 1) {
            // reduce over the 4 lanes of the quad (cols), leave on lane&3==0
            rs0 += __shfl_xor_sync(0xffffffffu, rs0, 1);
            rs0 += __shfl_xor_sync(0xffffffffu, rs0, 2);
            rs1 += __shfl_xor_sync(0xffffffffu, rs1, 1);
            rs1 += __shfl_xor_sync(0xffffffffu, rs1, 2);
            if ((lane & 3) == 0) {
                rs_sm[rt0 * 2 + warpN] = rs0;
                rs_sm[(rt0 + 8) * 2 + warpN] = rs1;
            }
        }
    }
    if (MODE == 1) {
        __syncthreads();
        if (tid < 128) {
            float2 v = reinterpret_cast<const float2*>(rs_sm)[tid];
            g_rsp[(size_t)(m0 + tid) * 8 + blockIdx.y] = v.x + v.y;
        }
    }
}

// ============================================================================
// Host launcher — fork/join second stream for conv+VWt overlap with
// rowsq+scores. Stream/events created on first (uncaptured) call only.
// ============================================================================
extern "C" void kernel_launch(void* const* d_in, const int* in_sizes, int n_in,
                              void* d_out, int out_size) {
    (void)in_sizes; (void)n_in; (void)out_size;
    const float* x      = (const float*)d_in[0];
    const float* pos    = (const float*)d_in[1];
    const float* scales = (const float*)d_in[2];
    const float* values = (const float*)d_in[3];
    const float* W      = (const float*)d_in[4];
    const float* b      = (const float*)d_in[5];
    float* out = (float*)d_out;

    static __half* vwt_p = nullptr;
    static __half* E_p   = nullptr;
    static float *xsq_p, *psq_p, *rsp_p;
    static __half *xb_p, *pb_p, *vb_p, *wb_p;
    static cudaStream_t s2;
    static cudaEvent_t eFork, eJoin;
    if (!vwt_p) {
        cudaGetSymbolAddress((void**)&vwt_p, g_vwt);
        cudaGetSymbolAddress((void**)&E_p,   g_E);
        cudaGetSymbolAddress((void**)&xsq_p, g_xsq);
        cudaGetSymbolAddress((void**)&psq_p, g_psq);
        cudaGetSymbolAddress((void**)&rsp_p, g_rsp);
        cudaGetSymbolAddress((void**)&xb_p,  g_xb);
        cudaGetSymbolAddress((void**)&pb_p,  g_pb);
        cudaGetSymbolAddress((void**)&vb_p,  g_vb);
        cudaGetSymbolAddress((void**)&wb_p,  g_wb);
        cudaStreamCreateWithFlags(&s2, cudaStreamNonBlocking);
        cudaEventCreateWithFlags(&eFork, cudaEventDisableTiming);
        cudaEventCreateWithFlags(&eJoin, cudaEventDisableTiming);
        cudaFuncSetAttribute(k_gemm<512, 0>,
            cudaFuncAttributeMaxDynamicSharedMemorySize, SMEM_SZ);
        cudaFuncSetAttribute(k_gemm<512, 1>,
            cudaFuncAttributeMaxDynamicSharedMemorySize, SMEM_SZ);
        cudaFuncSetAttribute(k_gemm<1024, 2>,
            cudaFuncAttributeMaxDynamicSharedMemorySize, SMEM_SZ);
    }

    // fork side stream: conv -> VWt GEMM (independent of x path)
    cudaEventRecord(eFork, 0);
    cudaStreamWaitEvent(s2, eFork, 0);
    k_conv<<<((NNEU * DIM + DIM * DIM) / 4) / 256, 256, 0, s2>>>(values, W);
    k_gemm<512, 0><<<dim3(4, 8), 256, SMEM_SZ, s2>>>(
        wb_p, vb_p, vwt_p, nullptr, nullptr, nullptr);
    cudaEventRecord(eJoin, s2);

    // main stream: rowsq -> scores
    k_rowsq<<<(MTOT + NNEU) / 8, 256>>>(x, pos);
    k_gemm<512, 1><<<dim3(128, 8), 256, SMEM_SZ>>>(
        xb_p, pb_p, E_p, xsq_p, psq_p, scales);

    // join, then out = E @ VWt^T / rowsum + b   (rowsum inlined from g_rsp)
    cudaStreamWaitEvent(0, eJoin, 0);
    k_gemm<1024, 2><<<dim3(128, 4), 256, SMEM_SZ>>>(
        E_p, vwt_p, out, rsp_p, b, nullptr);
}